// round 7
// baseline (speedup 1.0000x reference)
#include <cuda_runtime.h>
#include <cuda_fp16.h>
#include <math.h>
#include <stdint.h>

// Problem dims
#define MDIM  16384
#define KDIM  784
#define KPAD  832                  // 13 chunks of 64 (zero padded)
#define NDIM  8192
#define CDIM  10
#define NK1   (NDIM * KDIM)        // 6,422,528
#define NK2   (CDIM * NDIM)        // 81,920
#define J1    3211264u             // int(0.5 * NK1)
#define J2    40960u               // int(0.5 * NK2)

// GEMM tiling (legacy mma.sync fp16->fp32, m16n8k16), 512 threads, 64x32 warp tiles
#define BM 128
#define BN 256
#define KCH 64
#define NITER (KPAD / KCH)         // 13
#define STAGES 4
#define NT2 (NDIM / BN)            // 32 N-tiles
#define GTHREADS 512

// smem layout (dynamic) for GEMM
#define OFF_A 0                                   // STAGES x 16384
#define OFF_B (STAGES * 16384)                    // STAGES x 32768
#define OFF_W2 (OFF_B + STAGES * 32768)           // 196608
#define OFF_PART (OFF_W2 + CDIM * BN * 4)         // 206848
#define SMEM_TOTAL (OFF_PART + BM * CDIM * 4)     // 211968

#define SEL_NB 592                 // co-resident blocks for persistent select
#define W1_BLOCKS (NDIM * (KPAD / 4) / 256)       // 6656
#define XH_BLOCKS (MDIM * (KPAD / 8) / 256)       // 6656

// ---------------- scratch (device globals; no allocation allowed) ----------------
__device__ __half   g_xh[MDIM * KPAD];
__device__ __half   g_w1h[NDIM * KPAD];
__device__ float    g_w2m[CDIM * NDIM];
__device__ float    g_part[NT2 * MDIM * CDIM];
__device__ unsigned g_h1024[1024];
__device__ unsigned g_prefix;
__device__ unsigned g_rank;
__device__ unsigned g_nLess;
__device__ unsigned g_nTie;
__device__ unsigned g_T[2];
__device__ unsigned g_cutoff[2];
__device__ unsigned g_tieIdx[8192];
__device__ unsigned g_bar_cnt;
__device__ unsigned g_bar_gen;

__device__ __forceinline__ unsigned fbits_abs(float v) {
    return __float_as_uint(fabsf(v));
}
__device__ __forceinline__ uint32_t smem_u32(const void* p) {
    uint32_t a;
    asm("{ .reg .u64 t; cvta.to.shared.u64 t, %1; cvt.u32.u64 %0, t; }" : "=r"(a) : "l"(p));
    return a;
}

// ---------------- software grid barrier (all SEL_NB blocks co-resident) ----------------
__device__ __forceinline__ void grid_bar() {
    __syncthreads();
    if (threadIdx.x == 0) {
        unsigned gen = *((volatile unsigned*)&g_bar_gen);
        __threadfence();
        unsigned a = atomicAdd(&g_bar_cnt, 1u);
        if (a == SEL_NB - 1) {
            g_bar_cnt = 0;
            __threadfence();
            atomicAdd(&g_bar_gen, 1u);
        } else {
            while (*((volatile unsigned*)&g_bar_gen) == gen) { }
        }
        __threadfence();
    }
    __syncthreads();
}

// ---------------- persistent exact radix select for s1 (3 x 10-bit passes + ties) ----------------
__global__ void __launch_bounds__(256) k_select(const float* __restrict__ s, int n,
                                                unsigned j, int sel) {
    __shared__ unsigned h[1024];
    __shared__ unsigned sc[256];
    const int tid = threadIdx.x;
    const int gstride = SEL_NB * 256;
    const int gbase = blockIdx.x * 256 + tid;
    const float4* s4 = (const float4*)s;
    const int n4 = n >> 2;

    if (blockIdx.x == 0) {
        for (int b = tid; b < 1024; b += 256) g_h1024[b] = 0u;
        if (tid == 0) { g_prefix = 0u; g_rank = j; g_nLess = 0u; g_nTie = 0u; }
    }
    grid_bar();

#pragma unroll 1
    for (int pass = 0; pass < 3; pass++) {
        const int shift = 20 - 10 * pass;
        const unsigned prefix = g_prefix;
        for (int b = tid; b < 1024; b += 256) h[b] = 0u;
        __syncthreads();
        for (int i = gbase; i < n4; i += gstride) {
            float4 v = s4[i];
            unsigned b0 = fbits_abs(v.x), b1 = fbits_abs(v.y);
            unsigned b2 = fbits_abs(v.z), b3 = fbits_abs(v.w);
            if (pass == 0) {
                atomicAdd(&h[b0 >> 20], 1u); atomicAdd(&h[b1 >> 20], 1u);
                atomicAdd(&h[b2 >> 20], 1u); atomicAdd(&h[b3 >> 20], 1u);
            } else {
                if (((b0 ^ prefix) >> (shift + 10)) == 0u) atomicAdd(&h[(b0 >> shift) & 1023u], 1u);
                if (((b1 ^ prefix) >> (shift + 10)) == 0u) atomicAdd(&h[(b1 >> shift) & 1023u], 1u);
                if (((b2 ^ prefix) >> (shift + 10)) == 0u) atomicAdd(&h[(b2 >> shift) & 1023u], 1u);
                if (((b3 ^ prefix) >> (shift + 10)) == 0u) atomicAdd(&h[(b3 >> shift) & 1023u], 1u);
            }
        }
        __syncthreads();
        for (int b = tid; b < 1024; b += 256)
            if (h[b]) atomicAdd(&g_h1024[b], h[b]);
        grid_bar();

        if (blockIdx.x == 0) {
            unsigned c0 = g_h1024[4 * tid + 0], c1 = g_h1024[4 * tid + 1];
            unsigned c2 = g_h1024[4 * tid + 2], c3 = g_h1024[4 * tid + 3];
            unsigned mysum = c0 + c1 + c2 + c3;
            sc[tid] = mysum;
            __syncthreads();
#pragma unroll
            for (int off = 1; off < 256; off <<= 1) {
                unsigned v = (tid >= off) ? sc[tid - off] : 0u;
                __syncthreads();
                sc[tid] += v;
                __syncthreads();
            }
            unsigned incl = sc[tid], excl = incl - mysum;
            unsigned r = g_rank;
            if (excl <= r && r < incl) {
                unsigned d, cum = excl;
                if (r < cum + c0) { d = 4 * tid + 0; }
                else if (r < cum + c0 + c1) { d = 4 * tid + 1; cum += c0; }
                else if (r < cum + c0 + c1 + c2) { d = 4 * tid + 2; cum += c0 + c1; }
                else { d = 4 * tid + 3; cum += c0 + c1 + c2; }
                g_prefix = g_prefix | (d << shift);
                g_rank = r - cum;
            }
            __syncthreads();
            for (int b = tid; b < 1024; b += 256) g_h1024[b] = 0u;
            __threadfence();
        }
        grid_bar();
    }

    const unsigned T = g_prefix;
    unsigned nless = 0u;
    for (int i = gbase; i < n; i += gstride) {
        unsigned bits = fbits_abs(s[i]);
        if (bits < T) nless++;
        else if (bits == T) {
            unsigned p = atomicAdd(&g_nTie, 1u);
            if (p < 8192u) g_tieIdx[p] = (unsigned)i;
        }
    }
    sc[tid] = nless;
    __syncthreads();
#pragma unroll
    for (int off = 128; off > 0; off >>= 1) {
        if (tid < off) sc[tid] += sc[tid + off];
        __syncthreads();
    }
    if (tid == 0 && sc[0]) atomicAdd(&g_nLess, sc[0]);
    grid_bar();

    if (blockIdx.x == 0) {
        unsigned nLess = g_nLess;
        unsigned nTie = g_nTie; if (nTie > 8192u) nTie = 8192u;
        unsigned r2 = j - nLess;
        if (tid == 0) {
            g_T[sel] = T;
            if (r2 >= nTie) g_cutoff[sel] = 0xFFFFFFFFu;
        }
        __syncthreads();
        if (r2 < nTie) {
            for (unsigned t = tid; t < nTie; t += 256u) {
                unsigned mi = g_tieIdx[t];
                unsigned cnt = 0;
                for (unsigned u = 0; u < nTie; u++) cnt += (g_tieIdx[u] < mi) ? 1u : 0u;
                if (cnt == r2) g_cutoff[sel] = mi;
            }
        }
    }
}

// ---------------- single-block select for s2 + fused w2 mask build ----------------
__global__ void __launch_bounds__(1024) k_select2_w2m(const float* __restrict__ s,
                                                      const float* __restrict__ w2,
                                                      int n, unsigned j) {
    __shared__ unsigned h[1024];
    __shared__ unsigned sc[1024];
    __shared__ unsigned tie[4096];
    __shared__ unsigned sPrefix, sRank, sNTie, sNLess, sCut;
    const int tid = threadIdx.x;
    const float4* s4 = (const float4*)s;
    const int n4 = n >> 2;

    if (tid == 0) { sPrefix = 0u; sRank = j; sNTie = 0u; sNLess = 0u; sCut = 0xFFFFFFFFu; }
    __syncthreads();

#pragma unroll 1
    for (int pass = 0; pass < 3; pass++) {
        const int shift = 20 - 10 * pass;
        const unsigned prefix = sPrefix;
        h[tid] = 0u;
        __syncthreads();
        for (int i = tid; i < n4; i += 1024) {
            float4 v = s4[i];
            unsigned b0 = fbits_abs(v.x), b1 = fbits_abs(v.y);
            unsigned b2 = fbits_abs(v.z), b3 = fbits_abs(v.w);
            if (pass == 0) {
                atomicAdd(&h[b0 >> 20], 1u); atomicAdd(&h[b1 >> 20], 1u);
                atomicAdd(&h[b2 >> 20], 1u); atomicAdd(&h[b3 >> 20], 1u);
            } else {
                if (((b0 ^ prefix) >> (shift + 10)) == 0u) atomicAdd(&h[(b0 >> shift) & 1023u], 1u);
                if (((b1 ^ prefix) >> (shift + 10)) == 0u) atomicAdd(&h[(b1 >> shift) & 1023u], 1u);
                if (((b2 ^ prefix) >> (shift + 10)) == 0u) atomicAdd(&h[(b2 >> shift) & 1023u], 1u);
                if (((b3 ^ prefix) >> (shift + 10)) == 0u) atomicAdd(&h[(b3 >> shift) & 1023u], 1u);
            }
        }
        __syncthreads();
        unsigned mine = h[tid];
        sc[tid] = mine;
        __syncthreads();
#pragma unroll
        for (int off = 1; off < 1024; off <<= 1) {
            unsigned v = (tid >= off) ? sc[tid - off] : 0u;
            __syncthreads();
            sc[tid] += v;
            __syncthreads();
        }
        unsigned incl = sc[tid], excl = incl - mine;
        unsigned r = sRank;
        __syncthreads();
        if (excl <= r && r < incl) {
            sPrefix = prefix | ((unsigned)tid << shift);
            sRank = r - excl;
        }
        __syncthreads();
    }

    const unsigned T = sPrefix;
    unsigned nless = 0u;
    for (int i = tid; i < n; i += 1024) {
        unsigned bits = fbits_abs(s[i]);
        if (bits < T) nless++;
        else if (bits == T) {
            unsigned p = atomicAdd(&sNTie, 1u);
            if (p < 4096u) tie[p] = (unsigned)i;
        }
    }
    sc[tid] = nless;
    __syncthreads();
#pragma unroll
    for (int off = 512; off > 0; off >>= 1) {
        if (tid < off) sc[tid] += sc[tid + off];
        __syncthreads();
    }
    if (tid == 0) sNLess = sc[0];
    __syncthreads();

    {
        unsigned nTie = sNTie; if (nTie > 4096u) nTie = 4096u;
        unsigned r2 = j - sNLess;
        if (r2 < nTie) {
            for (unsigned t = tid; t < nTie; t += 1024u) {
                unsigned mi = tie[t];
                unsigned cnt = 0;
                for (unsigned u = 0; u < nTie; u++) cnt += (tie[u] < mi) ? 1u : 0u;
                if (cnt == r2) sCut = mi;
            }
        }
    }
    __syncthreads();
    const unsigned cut = sCut;
    if (tid == 0) { g_T[1] = T; g_cutoff[1] = cut; }

    for (int i = tid; i < n; i += 1024) {
        unsigned bits = fbits_abs(s[i]);
        bool keep = (bits > T) || (bits == T && (unsigned)i >= cut);
        g_w2m[i] = keep ? w2[i] : 0.0f;
    }
}

// ---------------- fused prep: masked fp16 w1 + fp16 x (both KPAD layout) ----------------
__global__ void __launch_bounds__(256) k_prep(const float* __restrict__ w1,
                                              const float* __restrict__ s1,
                                              const float* __restrict__ x) {
    const int b = blockIdx.x;
    const int tid = threadIdx.x;
    if (b < W1_BLOCKS) {
        int i = b * 256 + tid;
        int row = i / (KPAD / 4), k4 = (i % (KPAD / 4)) * 4;
        __half2 o[2];
        if (k4 < KDIM) {
            int src = row * KDIM + k4;
            float4 w = *(const float4*)(w1 + src);
            float4 sv = *(const float4*)(s1 + src);
            unsigned T = g_T[0], cut = g_cutoff[0];
            unsigned b0 = fbits_abs(sv.x), b1 = fbits_abs(sv.y);
            unsigned b2 = fbits_abs(sv.z), b3 = fbits_abs(sv.w);
            float f0 = ((b0 > T) || (b0 == T && (unsigned)(src + 0) >= cut)) ? w.x : 0.0f;
            float f1 = ((b1 > T) || (b1 == T && (unsigned)(src + 1) >= cut)) ? w.y : 0.0f;
            float f2 = ((b2 > T) || (b2 == T && (unsigned)(src + 2) >= cut)) ? w.z : 0.0f;
            float f3 = ((b3 > T) || (b3 == T && (unsigned)(src + 3) >= cut)) ? w.w : 0.0f;
            o[0] = __floats2half2_rn(f0, f1);
            o[1] = __floats2half2_rn(f2, f3);
        } else {
            o[0] = o[1] = __floats2half2_rn(0.0f, 0.0f);
        }
        *(uint2*)(g_w1h + (size_t)row * KPAD + k4) = *(const uint2*)o;
    } else {
        int i = (b - W1_BLOCKS) * 256 + tid;
        int row = i / (KPAD / 8), u = i % (KPAD / 8);
        int c8 = u * 8;
        __half2 h[4];
        if (c8 < KDIM) {
            const float4* p = (const float4*)(x + (size_t)row * KDIM + c8);
            float4 v0 = p[0], v1 = p[1];
            h[0] = __floats2half2_rn(v0.x, v0.y);
            h[1] = __floats2half2_rn(v0.z, v0.w);
            h[2] = __floats2half2_rn(v1.x, v1.y);
            h[3] = __floats2half2_rn(v1.z, v1.w);
        } else {
            h[0] = h[1] = h[2] = h[3] = __floats2half2_rn(0.0f, 0.0f);
        }
        *(uint4*)(g_xh + (size_t)row * KPAD + c8) = *(const uint4*)h;
    }
}

// ---------------- GEMM helpers ----------------
__device__ __forceinline__ void cp16(uint32_t dst, const void* src) {
    asm volatile("cp.async.cg.shared.global [%0], [%1], 16;" :: "r"(dst), "l"(src));
}
#define CP_COMMIT() asm volatile("cp.async.commit_group;" ::: "memory")
#define CP_WAIT(n)  asm volatile("cp.async.wait_group %0;" :: "n"(n) : "memory")

__device__ __forceinline__ void ldsm4(unsigned& r0, unsigned& r1, unsigned& r2, unsigned& r3,
                                      uint32_t addr) {
    asm volatile("ldmatrix.sync.aligned.m8n8.x4.shared.b16 {%0,%1,%2,%3}, [%4];"
                 : "=r"(r0), "=r"(r1), "=r"(r2), "=r"(r3) : "r"(addr));
}

__device__ __forceinline__ void mma_fp16(float* d, const unsigned* a, const unsigned* b) {
    asm volatile(
        "mma.sync.aligned.m16n8k16.row.col.f32.f16.f16.f32 "
        "{%0,%1,%2,%3}, {%4,%5,%6,%7}, {%8,%9}, {%0,%1,%2,%3};\n"
        : "+f"(d[0]), "+f"(d[1]), "+f"(d[2]), "+f"(d[3])
        : "r"(a[0]), "r"(a[1]), "r"(a[2]), "r"(a[3]), "r"(b[0]), "r"(b[1]));
}

__device__ __forceinline__ uint32_t sw_off(uint32_t row, uint32_t u) {
    return row * 128u + ((u ^ (row & 7u)) << 4);
}

// ---------------- GEMM1: 512 threads, 16 warps, 64x32 warp tiles, fp32 acc ----------------
__global__ void __launch_bounds__(GTHREADS, 1) k_gemm1() {
    extern __shared__ __align__(1024) char smem[];
    const uint32_t sb = smem_u32(smem);
    const int tid = threadIdx.x;
    const int nt = blockIdx.x;
    const int mt = blockIdx.y;

    const int wid = tid >> 5, lane = tid & 31;
    const int mw = wid & 1;      // 2 M warp-blocks of 64
    const int nw = wid >> 1;     // 8 N warp-blocks of 32
    const int g4 = lane >> 2, t4 = lane & 3;
    const int r8 = lane & 7;

    float* W2s  = (float*)(smem + OFF_W2);
    float* Part = (float*)(smem + OFF_PART);
    for (int p = tid; p < CDIM * BN; p += GTHREADS)
        W2s[p] = g_w2m[(p >> 8) * NDIM + nt * BN + (p & 255)];
    for (int p = tid; p < BM * CDIM; p += GTHREADS)
        Part[p] = 0.0f;

    const char* Ag = (const char*)(g_xh  + (size_t)(mt * BM) * KPAD);
    const char* Bg = (const char*)(g_w1h + (size_t)(nt * BN) * KPAD);
    const size_t rowBytes = KPAD * 2;

    const uint32_t aRowL = (uint32_t)(mw * 64 + ((lane >> 3) & 1) * 8 + r8);
    const uint32_t uA    = (uint32_t)(lane >> 4);
    const uint32_t bRowL = (uint32_t)(nw * 32 + (lane >> 4) * 8 + r8);
    const uint32_t uB    = (uint32_t)((lane >> 3) & 1);

    float d[4][4][4];
#pragma unroll
    for (int i = 0; i < 4; i++)
#pragma unroll
        for (int j = 0; j < 4; j++)
#pragma unroll
            for (int r = 0; r < 4; r++) d[i][j][r] = 0.0f;

#define ISSUE_STAGE(st) do {                                                      \
    const int _s = (st) & (STAGES - 1);                                           \
    const char* _ab = Ag + (size_t)(st) * 128;                                    \
    const char* _bb = Bg + (size_t)(st) * 128;                                    \
    _Pragma("unroll")                                                             \
    for (int q = 0; q < 2; q++) {                                                 \
        int idx = tid + q * GTHREADS;                                             \
        uint32_t row = (uint32_t)(idx >> 3), u = (uint32_t)(idx & 7);             \
        cp16(sb + OFF_A + _s * 16384 + sw_off(row, u),                            \
             _ab + (size_t)row * rowBytes + u * 16);                              \
    }                                                                             \
    _Pragma("unroll")                                                             \
    for (int q = 0; q < 4; q++) {                                                 \
        int idx = tid + q * GTHREADS;                                             \
        uint32_t row = (uint32_t)(idx >> 3), u = (uint32_t)(idx & 7);             \
        cp16(sb + OFF_B + _s * 32768 + sw_off(row, u),                            \
             _bb + (size_t)row * rowBytes + u * 16);                              \
    }                                                                             \
} while (0)

    ISSUE_STAGE(0); CP_COMMIT();
    ISSUE_STAGE(1); CP_COMMIT();
    ISSUE_STAGE(2); CP_COMMIT();

    for (int kk = 0; kk < NITER; kk++) {
        CP_WAIT(2);
        __syncthreads();
        const int nx = kk + 3;
        if (nx < NITER) { ISSUE_STAGE(nx); CP_COMMIT(); }

        const uint32_t aB = sb + OFF_A + (kk & 3) * 16384;
        const uint32_t bB = sb + OFF_B + (kk & 3) * 32768;
#pragma unroll
        for (int ks = 0; ks < 4; ks++) {
            const uint32_t ul = (uint32_t)(2 * ks);
            unsigned A4[4][4], B4[2][4];
#pragma unroll
            for (int i = 0; i < 4; i++) {
                uint32_t row = aRowL + (uint32_t)(i * 16);
                ldsm4(A4[i][0], A4[i][1], A4[i][2], A4[i][3],
                      aB + sw_off(row, ul + uA));
            }
#pragma unroll
            for (int j2 = 0; j2 < 2; j2++) {
                uint32_t row = bRowL + (uint32_t)(j2 * 16);
                ldsm4(B4[j2][0], B4[j2][1], B4[j2][2], B4[j2][3],
                      bB + sw_off(row, ul + uB));
            }
#pragma unroll
            for (int i = 0; i < 4; i++)
#pragma unroll
                for (int j = 0; j < 4; j++)
                    mma_fp16(d[i][j], A4[i], &B4[j >> 1][2 * (j & 1)]);
        }
    }

    // ---- epilogue: relu + contract with w2 slice ----
#pragma unroll
    for (int i = 0; i < 4; i++) {
#pragma unroll
        for (int h = 0; h < 2; h++) {
            const int row = mw * 64 + i * 16 + g4 + h * 8;
            float v0[4], v1[4];
#pragma unroll
            for (int j = 0; j < 4; j++) {
                v0[j] = fmaxf(d[i][j][2 * h + 0], 0.0f);
                v1[j] = fmaxf(d[i][j][2 * h + 1], 0.0f);
            }
#pragma unroll
            for (int c = 0; c < CDIM; c++) {
                float s = 0.0f;
#pragma unroll
                for (int j = 0; j < 4; j++) {
                    float2 w = *(const float2*)&W2s[c * BN + nw * 32 + j * 8 + 2 * t4];
                    s += v0[j] * w.x + v1[j] * w.y;
                }
                s += __shfl_xor_sync(0xFFFFFFFFu, s, 1);
                s += __shfl_xor_sync(0xFFFFFFFFu, s, 2);
                if (t4 == 0) atomicAdd(&Part[row * CDIM + c], s);
            }
        }
    }
    __syncthreads();

    float* outp = g_part + (size_t)nt * (MDIM * CDIM) + (size_t)(mt * BM) * CDIM;
    for (int p = tid; p < BM * CDIM; p += GTHREADS) outp[p] = Part[p];
#undef ISSUE_STAGE
}

// ---------------- reduce partials + log_softmax ----------------
__global__ void k_reduce(float* __restrict__ out) {   // <<<512, 320>>>
    const int tid = threadIdx.x;
    const int base = blockIdx.x * 32 * CDIM;
    float s = 0.0f;
#pragma unroll 8
    for (int nt = 0; nt < NT2; nt++)
        s += g_part[(size_t)nt * (MDIM * CDIM) + base + tid];
    __shared__ float L[32 * CDIM];
    L[tid] = s;
    __syncthreads();
    const int rl = tid / CDIM;
    float m = -INFINITY;
#pragma unroll
    for (int c = 0; c < CDIM; c++) m = fmaxf(m, L[rl * CDIM + c]);
    float se = 0.0f;
#pragma unroll
    for (int c = 0; c < CDIM; c++) se += expf(L[rl * CDIM + c] - m);
    out[base + tid] = s - m - logf(se);
}

// ---------------- launch ----------------
extern "C" void kernel_launch(void* const* d_in, const int* in_sizes, int n_in,
                              void* d_out, int out_size) {
    const float* x  = (const float*)d_in[0];
    const float* w1 = (const float*)d_in[1];
    const float* s1 = (const float*)d_in[2];
    const float* w2 = (const float*)d_in[3];
    const float* s2 = (const float*)d_in[4];
    float* out = (float*)d_out;

    cudaFuncSetAttribute(k_gemm1, cudaFuncAttributeMaxDynamicSharedMemorySize, SMEM_TOTAL);

    // launch order is load-bearing: ncu captures launch index 3 -> k_gemm1.
    k_select<<<SEL_NB, 256>>>(s1, NK1, J1, 0);                       // 0
    k_select2_w2m<<<1, 1024>>>(s2, w2, NK2, J2);                     // 1
    k_prep<<<W1_BLOCKS + XH_BLOCKS, 256>>>(w1, s1, x);               // 2
    dim3 grid(NT2, MDIM / BM);
    k_gemm1<<<grid, GTHREADS, SMEM_TOTAL>>>();                       // 3  <- ncu target
    k_reduce<<<MDIM / 32, 32 * CDIM>>>(out);                         // 4
}

// round 8
// speedup vs baseline: 1.0719x; 1.0719x over previous
#include <cuda_runtime.h>
#include <cuda_fp16.h>
#include <math.h>
#include <stdint.h>

// Problem dims
#define MDIM  16384
#define KDIM  784
#define KPAD  832                  // 13 chunks of 64 (zero padded)
#define NDIM  8192
#define CDIM  10
#define NK1   (NDIM * KDIM)        // 6,422,528
#define NK2   (CDIM * NDIM)        // 81,920
#define J1    3211264u             // int(0.5 * NK1)
#define J2    40960u               // int(0.5 * NK2)

// GEMM tiling: CTA 128x128, 256 threads, 8 warps as 2(M)x4(N), warp tile 64x32
// fp16 accumulate within each K=64 stage, promote to fp32 between stages.
#define BM 128
#define BN 128
#define KCH 64
#define NITER (KPAD / KCH)         // 13
#define STAGES 4
#define NT2 (NDIM / BN)            // 64 N-tiles
#define GTHREADS 256

// smem layout (dynamic) for GEMM; stage = 128 rows x 128B = 16KB each for A and B
#define OFF_A 0                                   // STAGES x 16384
#define OFF_B (STAGES * 16384)                    // STAGES x 16384
#define OFF_W2 (OFF_B + STAGES * 16384)           // 131072
#define OFF_PART (OFF_W2 + CDIM * BN * 4)         // 136192
#define SMEM_TOTAL (OFF_PART + BM * CDIM * 4)     // 141312

#define SEL_NB 592                 // co-resident blocks for persistent select
#define W1_BLOCKS (NDIM * (KPAD / 4) / 256)       // 6656
#define XH_BLOCKS (MDIM * (KPAD / 8) / 256)       // 6656

// ---------------- scratch (device globals; no allocation allowed) ----------------
__device__ __half   g_xh[MDIM * KPAD];
__device__ __half   g_w1h[NDIM * KPAD];
__device__ float    g_w2m[CDIM * NDIM];
__device__ float    g_part[NT2 * MDIM * CDIM];
__device__ unsigned g_h1024[1024];
__device__ unsigned g_prefix;
__device__ unsigned g_rank;
__device__ unsigned g_nLess;
__device__ unsigned g_nTie;
__device__ unsigned g_T[2];
__device__ unsigned g_cutoff[2];
__device__ unsigned g_tieIdx[8192];
__device__ unsigned g_bar_cnt;
__device__ unsigned g_bar_gen;

__device__ __forceinline__ unsigned fbits_abs(float v) {
    return __float_as_uint(fabsf(v));
}
__device__ __forceinline__ uint32_t smem_u32(const void* p) {
    uint32_t a;
    asm("{ .reg .u64 t; cvta.to.shared.u64 t, %1; cvt.u32.u64 %0, t; }" : "=r"(a) : "l"(p));
    return a;
}

// ---------------- software grid barrier (all SEL_NB blocks co-resident) ----------------
__device__ __forceinline__ void grid_bar() {
    __syncthreads();
    if (threadIdx.x == 0) {
        unsigned gen = *((volatile unsigned*)&g_bar_gen);
        __threadfence();
        unsigned a = atomicAdd(&g_bar_cnt, 1u);
        if (a == SEL_NB - 1) {
            g_bar_cnt = 0;
            __threadfence();
            atomicAdd(&g_bar_gen, 1u);
        } else {
            while (*((volatile unsigned*)&g_bar_gen) == gen) { }
        }
        __threadfence();
    }
    __syncthreads();
}

// ---------------- persistent exact radix select for s1 (3 x 10-bit passes + ties) ----------------
__global__ void __launch_bounds__(256) k_select(const float* __restrict__ s, int n,
                                                unsigned j, int sel) {
    __shared__ unsigned h[1024];
    __shared__ unsigned sc[256];
    const int tid = threadIdx.x;
    const int gstride = SEL_NB * 256;
    const int gbase = blockIdx.x * 256 + tid;
    const float4* s4 = (const float4*)s;
    const int n4 = n >> 2;

    if (blockIdx.x == 0) {
        for (int b = tid; b < 1024; b += 256) g_h1024[b] = 0u;
        if (tid == 0) { g_prefix = 0u; g_rank = j; g_nLess = 0u; g_nTie = 0u; }
    }
    grid_bar();

#pragma unroll 1
    for (int pass = 0; pass < 3; pass++) {
        const int shift = 20 - 10 * pass;
        const unsigned prefix = g_prefix;
        for (int b = tid; b < 1024; b += 256) h[b] = 0u;
        __syncthreads();
        for (int i = gbase; i < n4; i += gstride) {
            float4 v = s4[i];
            unsigned b0 = fbits_abs(v.x), b1 = fbits_abs(v.y);
            unsigned b2 = fbits_abs(v.z), b3 = fbits_abs(v.w);
            if (pass == 0) {
                atomicAdd(&h[b0 >> 20], 1u); atomicAdd(&h[b1 >> 20], 1u);
                atomicAdd(&h[b2 >> 20], 1u); atomicAdd(&h[b3 >> 20], 1u);
            } else {
                if (((b0 ^ prefix) >> (shift + 10)) == 0u) atomicAdd(&h[(b0 >> shift) & 1023u], 1u);
                if (((b1 ^ prefix) >> (shift + 10)) == 0u) atomicAdd(&h[(b1 >> shift) & 1023u], 1u);
                if (((b2 ^ prefix) >> (shift + 10)) == 0u) atomicAdd(&h[(b2 >> shift) & 1023u], 1u);
                if (((b3 ^ prefix) >> (shift + 10)) == 0u) atomicAdd(&h[(b3 >> shift) & 1023u], 1u);
            }
        }
        __syncthreads();
        for (int b = tid; b < 1024; b += 256)
            if (h[b]) atomicAdd(&g_h1024[b], h[b]);
        grid_bar();

        if (blockIdx.x == 0) {
            unsigned c0 = g_h1024[4 * tid + 0], c1 = g_h1024[4 * tid + 1];
            unsigned c2 = g_h1024[4 * tid + 2], c3 = g_h1024[4 * tid + 3];
            unsigned mysum = c0 + c1 + c2 + c3;
            sc[tid] = mysum;
            __syncthreads();
#pragma unroll
            for (int off = 1; off < 256; off <<= 1) {
                unsigned v = (tid >= off) ? sc[tid - off] : 0u;
                __syncthreads();
                sc[tid] += v;
                __syncthreads();
            }
            unsigned incl = sc[tid], excl = incl - mysum;
            unsigned r = g_rank;
            if (excl <= r && r < incl) {
                unsigned d, cum = excl;
                if (r < cum + c0) { d = 4 * tid + 0; }
                else if (r < cum + c0 + c1) { d = 4 * tid + 1; cum += c0; }
                else if (r < cum + c0 + c1 + c2) { d = 4 * tid + 2; cum += c0 + c1; }
                else { d = 4 * tid + 3; cum += c0 + c1 + c2; }
                g_prefix = g_prefix | (d << shift);
                g_rank = r - cum;
            }
            __syncthreads();
            for (int b = tid; b < 1024; b += 256) g_h1024[b] = 0u;
            __threadfence();
        }
        grid_bar();
    }

    const unsigned T = g_prefix;
    unsigned nless = 0u;
    for (int i = gbase; i < n; i += gstride) {
        unsigned bits = fbits_abs(s[i]);
        if (bits < T) nless++;
        else if (bits == T) {
            unsigned p = atomicAdd(&g_nTie, 1u);
            if (p < 8192u) g_tieIdx[p] = (unsigned)i;
        }
    }
    sc[tid] = nless;
    __syncthreads();
#pragma unroll
    for (int off = 128; off > 0; off >>= 1) {
        if (tid < off) sc[tid] += sc[tid + off];
        __syncthreads();
    }
    if (tid == 0 && sc[0]) atomicAdd(&g_nLess, sc[0]);
    grid_bar();

    if (blockIdx.x == 0) {
        unsigned nLess = g_nLess;
        unsigned nTie = g_nTie; if (nTie > 8192u) nTie = 8192u;
        unsigned r2 = j - nLess;
        if (tid == 0) {
            g_T[sel] = T;
            if (r2 >= nTie) g_cutoff[sel] = 0xFFFFFFFFu;
        }
        __syncthreads();
        if (r2 < nTie) {
            for (unsigned t = tid; t < nTie; t += 256u) {
                unsigned mi = g_tieIdx[t];
                unsigned cnt = 0;
                for (unsigned u = 0; u < nTie; u++) cnt += (g_tieIdx[u] < mi) ? 1u : 0u;
                if (cnt == r2) g_cutoff[sel] = mi;
            }
        }
    }
}

// ---------------- single-block select for s2 + fused w2 mask build ----------------
__global__ void __launch_bounds__(1024) k_select2_w2m(const float* __restrict__ s,
                                                      const float* __restrict__ w2,
                                                      int n, unsigned j) {
    __shared__ unsigned h[1024];
    __shared__ unsigned sc[1024];
    __shared__ unsigned tie[4096];
    __shared__ unsigned sPrefix, sRank, sNTie, sNLess, sCut;
    const int tid = threadIdx.x;
    const float4* s4 = (const float4*)s;
    const int n4 = n >> 2;

    if (tid == 0) { sPrefix = 0u; sRank = j; sNTie = 0u; sNLess = 0u; sCut = 0xFFFFFFFFu; }
    __syncthreads();

#pragma unroll 1
    for (int pass = 0; pass < 3; pass++) {
        const int shift = 20 - 10 * pass;
        const unsigned prefix = sPrefix;
        h[tid] = 0u;
        __syncthreads();
        for (int i = tid; i < n4; i += 1024) {
            float4 v = s4[i];
            unsigned b0 = fbits_abs(v.x), b1 = fbits_abs(v.y);
            unsigned b2 = fbits_abs(v.z), b3 = fbits_abs(v.w);
            if (pass == 0) {
                atomicAdd(&h[b0 >> 20], 1u); atomicAdd(&h[b1 >> 20], 1u);
                atomicAdd(&h[b2 >> 20], 1u); atomicAdd(&h[b3 >> 20], 1u);
            } else {
                if (((b0 ^ prefix) >> (shift + 10)) == 0u) atomicAdd(&h[(b0 >> shift) & 1023u], 1u);
                if (((b1 ^ prefix) >> (shift + 10)) == 0u) atomicAdd(&h[(b1 >> shift) & 1023u], 1u);
                if (((b2 ^ prefix) >> (shift + 10)) == 0u) atomicAdd(&h[(b2 >> shift) & 1023u], 1u);
                if (((b3 ^ prefix) >> (shift + 10)) == 0u) atomicAdd(&h[(b3 >> shift) & 1023u], 1u);
            }
        }
        __syncthreads();
        unsigned mine = h[tid];
        sc[tid] = mine;
        __syncthreads();
#pragma unroll
        for (int off = 1; off < 1024; off <<= 1) {
            unsigned v = (tid >= off) ? sc[tid - off] : 0u;
            __syncthreads();
            sc[tid] += v;
            __syncthreads();
        }
        unsigned incl = sc[tid], excl = incl - mine;
        unsigned r = sRank;
        __syncthreads();
        if (excl <= r && r < incl) {
            sPrefix = prefix | ((unsigned)tid << shift);
            sRank = r - excl;
        }
        __syncthreads();
    }

    const unsigned T = sPrefix;
    unsigned nless = 0u;
    for (int i = tid; i < n; i += 1024) {
        unsigned bits = fbits_abs(s[i]);
        if (bits < T) nless++;
        else if (bits == T) {
            unsigned p = atomicAdd(&sNTie, 1u);
            if (p < 4096u) tie[p] = (unsigned)i;
        }
    }
    sc[tid] = nless;
    __syncthreads();
#pragma unroll
    for (int off = 512; off > 0; off >>= 1) {
        if (tid < off) sc[tid] += sc[tid + off];
        __syncthreads();
    }
    if (tid == 0) sNLess = sc[0];
    __syncthreads();

    {
        unsigned nTie = sNTie; if (nTie > 4096u) nTie = 4096u;
        unsigned r2 = j - sNLess;
        if (r2 < nTie) {
            for (unsigned t = tid; t < nTie; t += 1024u) {
                unsigned mi = tie[t];
                unsigned cnt = 0;
                for (unsigned u = 0; u < nTie; u++) cnt += (tie[u] < mi) ? 1u : 0u;
                if (cnt == r2) sCut = mi;
            }
        }
    }
    __syncthreads();
    const unsigned cut = sCut;
    if (tid == 0) { g_T[1] = T; g_cutoff[1] = cut; }

    for (int i = tid; i < n; i += 1024) {
        unsigned bits = fbits_abs(s[i]);
        bool keep = (bits > T) || (bits == T && (unsigned)i >= cut);
        g_w2m[i] = keep ? w2[i] : 0.0f;
    }
}

// ---------------- fused prep: masked fp16 w1 + fp16 x (both KPAD layout) ----------------
__global__ void __launch_bounds__(256) k_prep(const float* __restrict__ w1,
                                              const float* __restrict__ s1,
                                              const float* __restrict__ x) {
    const int b = blockIdx.x;
    const int tid = threadIdx.x;
    if (b < W1_BLOCKS) {
        int i = b * 256 + tid;
        int row = i / (KPAD / 4), k4 = (i % (KPAD / 4)) * 4;
        __half2 o[2];
        if (k4 < KDIM) {
            int src = row * KDIM + k4;
            float4 w = *(const float4*)(w1 + src);
            float4 sv = *(const float4*)(s1 + src);
            unsigned T = g_T[0], cut = g_cutoff[0];
            unsigned b0 = fbits_abs(sv.x), b1 = fbits_abs(sv.y);
            unsigned b2 = fbits_abs(sv.z), b3 = fbits_abs(sv.w);
            float f0 = ((b0 > T) || (b0 == T && (unsigned)(src + 0) >= cut)) ? w.x : 0.0f;
            float f1 = ((b1 > T) || (b1 == T && (unsigned)(src + 1) >= cut)) ? w.y : 0.0f;
            float f2 = ((b2 > T) || (b2 == T && (unsigned)(src + 2) >= cut)) ? w.z : 0.0f;
            float f3 = ((b3 > T) || (b3 == T && (unsigned)(src + 3) >= cut)) ? w.w : 0.0f;
            o[0] = __floats2half2_rn(f0, f1);
            o[1] = __floats2half2_rn(f2, f3);
        } else {
            o[0] = o[1] = __floats2half2_rn(0.0f, 0.0f);
        }
        *(uint2*)(g_w1h + (size_t)row * KPAD + k4) = *(const uint2*)o;
    } else {
        int i = (b - W1_BLOCKS) * 256 + tid;
        int row = i / (KPAD / 8), u = i % (KPAD / 8);
        int c8 = u * 8;
        __half2 h[4];
        if (c8 < KDIM) {
            const float4* p = (const float4*)(x + (size_t)row * KDIM + c8);
            float4 v0 = p[0], v1 = p[1];
            h[0] = __floats2half2_rn(v0.x, v0.y);
            h[1] = __floats2half2_rn(v0.z, v0.w);
            h[2] = __floats2half2_rn(v1.x, v1.y);
            h[3] = __floats2half2_rn(v1.z, v1.w);
        } else {
            h[0] = h[1] = h[2] = h[3] = __floats2half2_rn(0.0f, 0.0f);
        }
        *(uint4*)(g_xh + (size_t)row * KPAD + c8) = *(const uint4*)h;
    }
}

// ---------------- GEMM helpers ----------------
__device__ __forceinline__ void cp16(uint32_t dst, const void* src) {
    asm volatile("cp.async.cg.shared.global [%0], [%1], 16;" :: "r"(dst), "l"(src));
}
#define CP_COMMIT() asm volatile("cp.async.commit_group;" ::: "memory")
#define CP_WAIT(n)  asm volatile("cp.async.wait_group %0;" :: "n"(n) : "memory")

__device__ __forceinline__ void ldsm4(unsigned& r0, unsigned& r1, unsigned& r2, unsigned& r3,
                                      uint32_t addr) {
    asm volatile("ldmatrix.sync.aligned.m8n8.x4.shared.b16 {%0,%1,%2,%3}, [%4];"
                 : "=r"(r0), "=r"(r1), "=r"(r2), "=r"(r3) : "r"(addr));
}

// fp16-accumulating MMA: D,C are 2 regs (4 halves)
__device__ __forceinline__ void mma_fp16h(unsigned* d, const unsigned* a, const unsigned* b) {
    asm volatile(
        "mma.sync.aligned.m16n8k16.row.col.f16.f16.f16.f16 "
        "{%0,%1}, {%2,%3,%4,%5}, {%6,%7}, {%0,%1};\n"
        : "+r"(d[0]), "+r"(d[1])
        : "r"(a[0]), "r"(a[1]), "r"(a[2]), "r"(a[3]), "r"(b[0]), "r"(b[1]));
}

__device__ __forceinline__ uint32_t sw_off(uint32_t row, uint32_t u) {
    return row * 128u + ((u ^ (row & 7u)) << 4);
}

// ---------------- GEMM1: 256 threads, 8 warps, 64x32 warp tiles,
//                  fp16 stage-accumulate + fp32 promote ----------------
__global__ void __launch_bounds__(GTHREADS, 1) k_gemm1() {
    extern __shared__ __align__(1024) char smem[];
    const uint32_t sb = smem_u32(smem);
    const int tid = threadIdx.x;
    const int nt = blockIdx.x;   // 0..63 (N tiles of 128)
    const int mt = blockIdx.y;   // 0..127 (M tiles of 128)

    const int wid = tid >> 5, lane = tid & 31;
    const int mw = wid & 1;      // 2 M warp-blocks of 64
    const int nw = wid >> 1;     // 4 N warp-blocks of 32
    const int g4 = lane >> 2, t4 = lane & 3;
    const int r8 = lane & 7;

    float* W2s  = (float*)(smem + OFF_W2);
    float* Part = (float*)(smem + OFF_PART);
    for (int p = tid; p < CDIM * BN; p += GTHREADS)
        W2s[p] = g_w2m[(p >> 7) * NDIM + nt * BN + (p & 127)];
    for (int p = tid; p < BM * CDIM; p += GTHREADS)
        Part[p] = 0.0f;

    const char* Ag = (const char*)(g_xh  + (size_t)(mt * BM) * KPAD);
    const char* Bg = (const char*)(g_w1h + (size_t)(nt * BN) * KPAD);
    const size_t rowBytes = KPAD * 2;

    const uint32_t aRowL = (uint32_t)(mw * 64 + ((lane >> 3) & 1) * 8 + r8);
    const uint32_t uA    = (uint32_t)(lane >> 4);
    const uint32_t bRowL = (uint32_t)(nw * 32 + (lane >> 4) * 8 + r8);
    const uint32_t uB    = (uint32_t)((lane >> 3) & 1);

    float d[4][4][4];
#pragma unroll
    for (int i = 0; i < 4; i++)
#pragma unroll
        for (int j = 0; j < 4; j++)
#pragma unroll
            for (int r = 0; r < 4; r++) d[i][j][r] = 0.0f;

#define ISSUE_STAGE(st) do {                                                      \
    const int _s = (st) & (STAGES - 1);                                           \
    const char* _ab = Ag + (size_t)(st) * 128;                                    \
    const char* _bb = Bg + (size_t)(st) * 128;                                    \
    _Pragma("unroll")                                                             \
    for (int q = 0; q < 4; q++) {                                                 \
        int idx = tid + q * GTHREADS;                                             \
        uint32_t row = (uint32_t)(idx >> 3), u = (uint32_t)(idx & 7);             \
        cp16(sb + OFF_A + _s * 16384 + sw_off(row, u),                            \
             _ab + (size_t)row * rowBytes + u * 16);                              \
    }                                                                             \
    _Pragma("unroll")                                                             \
    for (int q = 0; q < 4; q++) {                                                 \
        int idx = tid + q * GTHREADS;                                             \
        uint32_t row = (uint32_t)(idx >> 3), u = (uint32_t)(idx & 7);             \
        cp16(sb + OFF_B + _s * 16384 + sw_off(row, u),                            \
             _bb + (size_t)row * rowBytes + u * 16);                              \
    }                                                                             \
} while (0)

    ISSUE_STAGE(0); CP_COMMIT();
    ISSUE_STAGE(1); CP_COMMIT();
    ISSUE_STAGE(2); CP_COMMIT();

    for (int kk = 0; kk < NITER; kk++) {
        CP_WAIT(2);
        __syncthreads();
        const int nx = kk + 3;
        if (nx < NITER) { ISSUE_STAGE(nx); CP_COMMIT(); }

        const uint32_t aB = sb + OFF_A + (kk & 3) * 16384;
        const uint32_t bB = sb + OFF_B + (kk & 3) * 16384;

        // fp16 accumulators for this K=64 stage (32 regs)
        unsigned dh[4][4][2];
#pragma unroll
        for (int i = 0; i < 4; i++)
#pragma unroll
            for (int j = 0; j < 4; j++) { dh[i][j][0] = 0u; dh[i][j][1] = 0u; }

#pragma unroll
        for (int ks = 0; ks < 4; ks++) {
            const uint32_t ul = (uint32_t)(2 * ks);
            unsigned A4[4][4], B4[2][4];
#pragma unroll
            for (int i = 0; i < 4; i++) {
                uint32_t row = aRowL + (uint32_t)(i * 16);
                ldsm4(A4[i][0], A4[i][1], A4[i][2], A4[i][3],
                      aB + sw_off(row, ul + uA));
            }
#pragma unroll
            for (int j2 = 0; j2 < 2; j2++) {
                uint32_t row = bRowL + (uint32_t)(j2 * 16);
                ldsm4(B4[j2][0], B4[j2][1], B4[j2][2], B4[j2][3],
                      bB + sw_off(row, ul + uB));
            }
#pragma unroll
            for (int i = 0; i < 4; i++)
#pragma unroll
                for (int j = 0; j < 4; j++)
                    mma_fp16h(dh[i][j], A4[i], &B4[j >> 1][2 * (j & 1)]);
        }

        // promote to fp32
#pragma unroll
        for (int i = 0; i < 4; i++)
#pragma unroll
            for (int j = 0; j < 4; j++) {
                float2 f0 = __half22float2(*(const __half2*)&dh[i][j][0]);
                float2 f1 = __half22float2(*(const __half2*)&dh[i][j][1]);
                d[i][j][0] += f0.x; d[i][j][1] += f0.y;
                d[i][j][2] += f1.x; d[i][j][3] += f1.y;
            }
    }

    // ---- epilogue: relu + contract with w2 slice ----
#pragma unroll
    for (int i = 0; i < 4; i++) {
#pragma unroll
        for (int h = 0; h < 2; h++) {
            const int row = mw * 64 + i * 16 + g4 + h * 8;
            float v0[4], v1[4];
#pragma unroll
            for (int j = 0; j < 4; j++) {
                v0[j] = fmaxf(d[i][j][2 * h + 0], 0.0f);
                v1[j] = fmaxf(d[i][j][2 * h + 1], 0.0f);
            }
#pragma unroll
            for (int c = 0; c < CDIM; c++) {
                float s = 0.0f;
#pragma unroll
                for (int j = 0; j < 4; j++) {
                    float2 w = *(const float2*)&W2s[c * BN + nw * 32 + j * 8 + 2 * t4];
                    s += v0[j] * w.x + v1[j] * w.y;
                }
                s += __shfl_xor_sync(0xFFFFFFFFu, s, 1);
                s += __shfl_xor_sync(0xFFFFFFFFu, s, 2);
                if (t4 == 0) atomicAdd(&Part[row * CDIM + c], s);
            }
        }
    }
    __syncthreads();

    float* outp = g_part + (size_t)nt * (MDIM * CDIM) + (size_t)(mt * BM) * CDIM;
    for (int p = tid; p < BM * CDIM; p += GTHREADS) outp[p] = Part[p];
#undef ISSUE_STAGE
}

// ---------------- reduce partials + log_softmax ----------------
__global__ void k_reduce(float* __restrict__ out) {   // <<<512, 320>>>
    const int tid = threadIdx.x;
    const int base = blockIdx.x * 32 * CDIM;
    float s = 0.0f;
#pragma unroll 8
    for (int nt = 0; nt < NT2; nt++)
        s += g_part[(size_t)nt * (MDIM * CDIM) + base + tid];
    __shared__ float L[32 * CDIM];
    L[tid] = s;
    __syncthreads();
    const int rl = tid / CDIM;
    float m = -INFINITY;
#pragma unroll
    for (int c = 0; c < CDIM; c++) m = fmaxf(m, L[rl * CDIM + c]);
    float se = 0.0f;
#pragma unroll
    for (int c = 0; c < CDIM; c++) se += expf(L[rl * CDIM + c] - m);
    out[base + tid] = s - m - logf(se);
}

// ---------------- launch ----------------
extern "C" void kernel_launch(void* const* d_in, const int* in_sizes, int n_in,
                              void* d_out, int out_size) {
    const float* x  = (const float*)d_in[0];
    const float* w1 = (const float*)d_in[1];
    const float* s1 = (const float*)d_in[2];
    const float* w2 = (const float*)d_in[3];
    const float* s2 = (const float*)d_in[4];
    float* out = (float*)d_out;

    cudaFuncSetAttribute(k_gemm1, cudaFuncAttributeMaxDynamicSharedMemorySize, SMEM_TOTAL);

    // launch order is load-bearing: ncu captures launch index 3 -> k_gemm1.
    k_select<<<SEL_NB, 256>>>(s1, NK1, J1, 0);                       // 0
    k_select2_w2m<<<1, 1024>>>(s2, w2, NK2, J2);                     // 1
    k_prep<<<W1_BLOCKS + XH_BLOCKS, 256>>>(w1, s1, x);               // 2
    dim3 grid(NT2, MDIM / BM);   // (64, 128)
    k_gemm1<<<grid, GTHREADS, SMEM_TOTAL>>>();                       // 3  <- ncu target
    k_reduce<<<MDIM / 32, 32 * CDIM>>>(out);                         // 4
}

// round 9
// speedup vs baseline: 1.3638x; 1.2723x over previous
#include <cuda_runtime.h>
#include <cuda_fp16.h>
#include <math.h>
#include <stdint.h>

// Problem dims
#define MDIM  16384
#define KDIM  784
#define KPAD  832                  // 13 chunks of 64 (zero padded)
#define NDIM  8192
#define CDIM  10
#define NK1   (NDIM * KDIM)        // 6,422,528
#define NK2   (CDIM * NDIM)        // 81,920
#define J1    3211264u             // int(0.5 * NK1)
#define J2    40960u               // int(0.5 * NK2)

// GEMM tiling: CTA 128x256, 256 threads, 8 warps as 2(M)x4(N), warp tile 64x64.
// fp16 accumulate per stage in two N-half passes (dh = 32 regs), promote to fp32.
#define BM 128
#define BN 256
#define KCH 64
#define NITER (KPAD / KCH)         // 13
#define STAGES 4
#define NT2 (NDIM / BN)            // 32 N-tiles
#define GTHREADS 256

// smem layout (dynamic) for GEMM
#define OFF_A 0                                   // STAGES x 16384
#define OFF_B (STAGES * 16384)                    // STAGES x 32768
#define OFF_W2 (OFF_B + STAGES * 32768)           // 196608
#define OFF_PART (OFF_W2 + CDIM * BN * 4)         // 206848
#define SMEM_TOTAL (OFF_PART + BM * CDIM * 4)     // 211968

#define SEL_NB 592                 // co-resident blocks for persistent select
#define W1_BLOCKS (NDIM * (KPAD / 4) / 256)       // 6656
#define XH_BLOCKS (MDIM * (KPAD / 8) / 256)       // 6656

// ---------------- scratch (device globals; no allocation allowed) ----------------
__device__ __half   g_xh[MDIM * KPAD];
__device__ __half   g_w1h[NDIM * KPAD];
__device__ float    g_w2m[CDIM * NDIM];
__device__ float    g_part[NT2 * MDIM * CDIM];
__device__ unsigned g_h1024[1024];
__device__ unsigned g_prefix;
__device__ unsigned g_rank;
__device__ unsigned g_nLess;
__device__ unsigned g_nTie;
__device__ unsigned g_T[2];
__device__ unsigned g_cutoff[2];
__device__ unsigned g_tieIdx[8192];
__device__ unsigned g_bar_cnt;
__device__ unsigned g_bar_gen;

__device__ __forceinline__ unsigned fbits_abs(float v) {
    return __float_as_uint(fabsf(v));
}
__device__ __forceinline__ uint32_t smem_u32(const void* p) {
    uint32_t a;
    asm("{ .reg .u64 t; cvta.to.shared.u64 t, %1; cvt.u32.u64 %0, t; }" : "=r"(a) : "l"(p));
    return a;
}

// ---------------- software grid barrier (all SEL_NB blocks co-resident) ----------------
__device__ __forceinline__ void grid_bar() {
    __syncthreads();
    if (threadIdx.x == 0) {
        unsigned gen = *((volatile unsigned*)&g_bar_gen);
        __threadfence();
        unsigned a = atomicAdd(&g_bar_cnt, 1u);
        if (a == SEL_NB - 1) {
            g_bar_cnt = 0;
            __threadfence();
            atomicAdd(&g_bar_gen, 1u);
        } else {
            while (*((volatile unsigned*)&g_bar_gen) == gen) { }
        }
        __threadfence();
    }
    __syncthreads();
}

// ---------------- persistent exact radix select for s1 (3 x 10-bit passes + ties) ----------------
__global__ void __launch_bounds__(256) k_select(const float* __restrict__ s, int n,
                                                unsigned j, int sel) {
    __shared__ unsigned h[1024];
    __shared__ unsigned sc[256];
    const int tid = threadIdx.x;
    const int gstride = SEL_NB * 256;
    const int gbase = blockIdx.x * 256 + tid;
    const float4* s4 = (const float4*)s;
    const int n4 = n >> 2;

    if (blockIdx.x == 0) {
        for (int b = tid; b < 1024; b += 256) g_h1024[b] = 0u;
        if (tid == 0) { g_prefix = 0u; g_rank = j; g_nLess = 0u; g_nTie = 0u; }
    }
    grid_bar();

#pragma unroll 1
    for (int pass = 0; pass < 3; pass++) {
        const int shift = 20 - 10 * pass;
        const unsigned prefix = g_prefix;
        for (int b = tid; b < 1024; b += 256) h[b] = 0u;
        __syncthreads();
        for (int i = gbase; i < n4; i += gstride) {
            float4 v = s4[i];
            unsigned b0 = fbits_abs(v.x), b1 = fbits_abs(v.y);
            unsigned b2 = fbits_abs(v.z), b3 = fbits_abs(v.w);
            if (pass == 0) {
                atomicAdd(&h[b0 >> 20], 1u); atomicAdd(&h[b1 >> 20], 1u);
                atomicAdd(&h[b2 >> 20], 1u); atomicAdd(&h[b3 >> 20], 1u);
            } else {
                if (((b0 ^ prefix) >> (shift + 10)) == 0u) atomicAdd(&h[(b0 >> shift) & 1023u], 1u);
                if (((b1 ^ prefix) >> (shift + 10)) == 0u) atomicAdd(&h[(b1 >> shift) & 1023u], 1u);
                if (((b2 ^ prefix) >> (shift + 10)) == 0u) atomicAdd(&h[(b2 >> shift) & 1023u], 1u);
                if (((b3 ^ prefix) >> (shift + 10)) == 0u) atomicAdd(&h[(b3 >> shift) & 1023u], 1u);
            }
        }
        __syncthreads();
        for (int b = tid; b < 1024; b += 256)
            if (h[b]) atomicAdd(&g_h1024[b], h[b]);
        grid_bar();

        if (blockIdx.x == 0) {
            unsigned c0 = g_h1024[4 * tid + 0], c1 = g_h1024[4 * tid + 1];
            unsigned c2 = g_h1024[4 * tid + 2], c3 = g_h1024[4 * tid + 3];
            unsigned mysum = c0 + c1 + c2 + c3;
            sc[tid] = mysum;
            __syncthreads();
#pragma unroll
            for (int off = 1; off < 256; off <<= 1) {
                unsigned v = (tid >= off) ? sc[tid - off] : 0u;
                __syncthreads();
                sc[tid] += v;
                __syncthreads();
            }
            unsigned incl = sc[tid], excl = incl - mysum;
            unsigned r = g_rank;
            if (excl <= r && r < incl) {
                unsigned d, cum = excl;
                if (r < cum + c0) { d = 4 * tid + 0; }
                else if (r < cum + c0 + c1) { d = 4 * tid + 1; cum += c0; }
                else if (r < cum + c0 + c1 + c2) { d = 4 * tid + 2; cum += c0 + c1; }
                else { d = 4 * tid + 3; cum += c0 + c1 + c2; }
                g_prefix = g_prefix | (d << shift);
                g_rank = r - cum;
            }
            __syncthreads();
            for (int b = tid; b < 1024; b += 256) g_h1024[b] = 0u;
            __threadfence();
        }
        grid_bar();
    }

    const unsigned T = g_prefix;
    unsigned nless = 0u;
    for (int i = gbase; i < n; i += gstride) {
        unsigned bits = fbits_abs(s[i]);
        if (bits < T) nless++;
        else if (bits == T) {
            unsigned p = atomicAdd(&g_nTie, 1u);
            if (p < 8192u) g_tieIdx[p] = (unsigned)i;
        }
    }
    sc[tid] = nless;
    __syncthreads();
#pragma unroll
    for (int off = 128; off > 0; off >>= 1) {
        if (tid < off) sc[tid] += sc[tid + off];
        __syncthreads();
    }
    if (tid == 0 && sc[0]) atomicAdd(&g_nLess, sc[0]);
    grid_bar();

    if (blockIdx.x == 0) {
        unsigned nLess = g_nLess;
        unsigned nTie = g_nTie; if (nTie > 8192u) nTie = 8192u;
        unsigned r2 = j - nLess;
        if (tid == 0) {
            g_T[sel] = T;
            if (r2 >= nTie) g_cutoff[sel] = 0xFFFFFFFFu;
        }
        __syncthreads();
        if (r2 < nTie) {
            for (unsigned t = tid; t < nTie; t += 256u) {
                unsigned mi = g_tieIdx[t];
                unsigned cnt = 0;
                for (unsigned u = 0; u < nTie; u++) cnt += (g_tieIdx[u] < mi) ? 1u : 0u;
                if (cnt == r2) g_cutoff[sel] = mi;
            }
        }
    }
}

// ---------------- single-block select for s2 + fused w2 mask build ----------------
__global__ void __launch_bounds__(1024) k_select2_w2m(const float* __restrict__ s,
                                                      const float* __restrict__ w2,
                                                      int n, unsigned j) {
    __shared__ unsigned h[1024];
    __shared__ unsigned sc[1024];
    __shared__ unsigned tie[4096];
    __shared__ unsigned sPrefix, sRank, sNTie, sNLess, sCut;
    const int tid = threadIdx.x;
    const float4* s4 = (const float4*)s;
    const int n4 = n >> 2;

    if (tid == 0) { sPrefix = 0u; sRank = j; sNTie = 0u; sNLess = 0u; sCut = 0xFFFFFFFFu; }
    __syncthreads();

#pragma unroll 1
    for (int pass = 0; pass < 3; pass++) {
        const int shift = 20 - 10 * pass;
        const unsigned prefix = sPrefix;
        h[tid] = 0u;
        __syncthreads();
        for (int i = tid; i < n4; i += 1024) {
            float4 v = s4[i];
            unsigned b0 = fbits_abs(v.x), b1 = fbits_abs(v.y);
            unsigned b2 = fbits_abs(v.z), b3 = fbits_abs(v.w);
            if (pass == 0) {
                atomicAdd(&h[b0 >> 20], 1u); atomicAdd(&h[b1 >> 20], 1u);
                atomicAdd(&h[b2 >> 20], 1u); atomicAdd(&h[b3 >> 20], 1u);
            } else {
                if (((b0 ^ prefix) >> (shift + 10)) == 0u) atomicAdd(&h[(b0 >> shift) & 1023u], 1u);
                if (((b1 ^ prefix) >> (shift + 10)) == 0u) atomicAdd(&h[(b1 >> shift) & 1023u], 1u);
                if (((b2 ^ prefix) >> (shift + 10)) == 0u) atomicAdd(&h[(b2 >> shift) & 1023u], 1u);
                if (((b3 ^ prefix) >> (shift + 10)) == 0u) atomicAdd(&h[(b3 >> shift) & 1023u], 1u);
            }
        }
        __syncthreads();
        unsigned mine = h[tid];
        sc[tid] = mine;
        __syncthreads();
#pragma unroll
        for (int off = 1; off < 1024; off <<= 1) {
            unsigned v = (tid >= off) ? sc[tid - off] : 0u;
            __syncthreads();
            sc[tid] += v;
            __syncthreads();
        }
        unsigned incl = sc[tid], excl = incl - mine;
        unsigned r = sRank;
        __syncthreads();
        if (excl <= r && r < incl) {
            sPrefix = prefix | ((unsigned)tid << shift);
            sRank = r - excl;
        }
        __syncthreads();
    }

    const unsigned T = sPrefix;
    unsigned nless = 0u;
    for (int i = tid; i < n; i += 1024) {
        unsigned bits = fbits_abs(s[i]);
        if (bits < T) nless++;
        else if (bits == T) {
            unsigned p = atomicAdd(&sNTie, 1u);
            if (p < 4096u) tie[p] = (unsigned)i;
        }
    }
    sc[tid] = nless;
    __syncthreads();
#pragma unroll
    for (int off = 512; off > 0; off >>= 1) {
        if (tid < off) sc[tid] += sc[tid + off];
        __syncthreads();
    }
    if (tid == 0) sNLess = sc[0];
    __syncthreads();

    {
        unsigned nTie = sNTie; if (nTie > 4096u) nTie = 4096u;
        unsigned r2 = j - sNLess;
        if (r2 < nTie) {
            for (unsigned t = tid; t < nTie; t += 1024u) {
                unsigned mi = tie[t];
                unsigned cnt = 0;
                for (unsigned u = 0; u < nTie; u++) cnt += (tie[u] < mi) ? 1u : 0u;
                if (cnt == r2) sCut = mi;
            }
        }
    }
    __syncthreads();
    const unsigned cut = sCut;
    if (tid == 0) { g_T[1] = T; g_cutoff[1] = cut; }

    for (int i = tid; i < n; i += 1024) {
        unsigned bits = fbits_abs(s[i]);
        bool keep = (bits > T) || (bits == T && (unsigned)i >= cut);
        g_w2m[i] = keep ? w2[i] : 0.0f;
    }
}

// ---------------- fused prep: masked fp16 w1 + fp16 x (both KPAD layout) ----------------
__global__ void __launch_bounds__(256) k_prep(const float* __restrict__ w1,
                                              const float* __restrict__ s1,
                                              const float* __restrict__ x) {
    const int b = blockIdx.x;
    const int tid = threadIdx.x;
    if (b < W1_BLOCKS) {
        int i = b * 256 + tid;
        int row = i / (KPAD / 4), k4 = (i % (KPAD / 4)) * 4;
        __half2 o[2];
        if (k4 < KDIM) {
            int src = row * KDIM + k4;
            float4 w = *(const float4*)(w1 + src);
            float4 sv = *(const float4*)(s1 + src);
            unsigned T = g_T[0], cut = g_cutoff[0];
            unsigned b0 = fbits_abs(sv.x), b1 = fbits_abs(sv.y);
            unsigned b2 = fbits_abs(sv.z), b3 = fbits_abs(sv.w);
            float f0 = ((b0 > T) || (b0 == T && (unsigned)(src + 0) >= cut)) ? w.x : 0.0f;
            float f1 = ((b1 > T) || (b1 == T && (unsigned)(src + 1) >= cut)) ? w.y : 0.0f;
            float f2 = ((b2 > T) || (b2 == T && (unsigned)(src + 2) >= cut)) ? w.z : 0.0f;
            float f3 = ((b3 > T) || (b3 == T && (unsigned)(src + 3) >= cut)) ? w.w : 0.0f;
            o[0] = __floats2half2_rn(f0, f1);
            o[1] = __floats2half2_rn(f2, f3);
        } else {
            o[0] = o[1] = __floats2half2_rn(0.0f, 0.0f);
        }
        *(uint2*)(g_w1h + (size_t)row * KPAD + k4) = *(const uint2*)o;
    } else {
        int i = (b - W1_BLOCKS) * 256 + tid;
        int row = i / (KPAD / 8), u = i % (KPAD / 8);
        int c8 = u * 8;
        __half2 h[4];
        if (c8 < KDIM) {
            const float4* p = (const float4*)(x + (size_t)row * KDIM + c8);
            float4 v0 = p[0], v1 = p[1];
            h[0] = __floats2half2_rn(v0.x, v0.y);
            h[1] = __floats2half2_rn(v0.z, v0.w);
            h[2] = __floats2half2_rn(v1.x, v1.y);
            h[3] = __floats2half2_rn(v1.z, v1.w);
        } else {
            h[0] = h[1] = h[2] = h[3] = __floats2half2_rn(0.0f, 0.0f);
        }
        *(uint4*)(g_xh + (size_t)row * KPAD + c8) = *(const uint4*)h;
    }
}

// ---------------- GEMM helpers ----------------
__device__ __forceinline__ void cp16(uint32_t dst, const void* src) {
    asm volatile("cp.async.cg.shared.global [%0], [%1], 16;" :: "r"(dst), "l"(src));
}
#define CP_COMMIT() asm volatile("cp.async.commit_group;" ::: "memory")
#define CP_WAIT(n)  asm volatile("cp.async.wait_group %0;" :: "n"(n) : "memory")

__device__ __forceinline__ void ldsm4(unsigned& r0, unsigned& r1, unsigned& r2, unsigned& r3,
                                      uint32_t addr) {
    asm volatile("ldmatrix.sync.aligned.m8n8.x4.shared.b16 {%0,%1,%2,%3}, [%4];"
                 : "=r"(r0), "=r"(r1), "=r"(r2), "=r"(r3) : "r"(addr));
}

// fp16-accumulating MMA: D,C are 2 regs (4 halves)
__device__ __forceinline__ void mma_fp16h(unsigned* d, const unsigned* a, const unsigned* b) {
    asm volatile(
        "mma.sync.aligned.m16n8k16.row.col.f16.f16.f16.f16 "
        "{%0,%1}, {%2,%3,%4,%5}, {%6,%7}, {%0,%1};\n"
        : "+r"(d[0]), "+r"(d[1])
        : "r"(a[0]), "r"(a[1]), "r"(a[2]), "r"(a[3]), "r"(b[0]), "r"(b[1]));
}

__device__ __forceinline__ uint32_t sw_off(uint32_t row, uint32_t u) {
    return row * 128u + ((u ^ (row & 7u)) << 4);
}

// ---------------- GEMM1: 256 threads, 8 warps of 64x64.
//  Each K=64 stage: two N-half passes with fp16 accumulators (32 regs),
//  promoted into resident fp32 d. A LDSM re-issued per half (asm volatile -> no CSE).
__global__ void __launch_bounds__(GTHREADS, 1) k_gemm1() {
    extern __shared__ __align__(1024) char smem[];
    const uint32_t sb = smem_u32(smem);
    const int tid = threadIdx.x;
    const int nt = blockIdx.x;   // 0..31 (N tiles of 256)
    const int mt = blockIdx.y;   // 0..127 (M tiles of 128)

    const int wid = tid >> 5, lane = tid & 31;
    const int mw = wid & 1;      // 2 M warp-blocks of 64
    const int nw = wid >> 1;     // 4 N warp-blocks of 64
    const int g4 = lane >> 2, t4 = lane & 3;
    const int r8 = lane & 7;

    float* W2s  = (float*)(smem + OFF_W2);
    float* Part = (float*)(smem + OFF_PART);
    for (int p = tid; p < CDIM * BN; p += GTHREADS)
        W2s[p] = g_w2m[(p >> 8) * NDIM + nt * BN + (p & 255)];
    for (int p = tid; p < BM * CDIM; p += GTHREADS)
        Part[p] = 0.0f;

    const char* Ag = (const char*)(g_xh  + (size_t)(mt * BM) * KPAD);
    const char* Bg = (const char*)(g_w1h + (size_t)(nt * BN) * KPAD);
    const size_t rowBytes = KPAD * 2;

    const uint32_t aRowL = (uint32_t)(mw * 64 + ((lane >> 3) & 1) * 8 + r8);
    const uint32_t uA    = (uint32_t)(lane >> 4);
    const uint32_t bRowL = (uint32_t)(nw * 64 + (lane >> 4) * 8 + r8);
    const uint32_t uB    = (uint32_t)((lane >> 3) & 1);

    float d[4][8][4];
#pragma unroll
    for (int i = 0; i < 4; i++)
#pragma unroll
        for (int j = 0; j < 8; j++)
#pragma unroll
            for (int r = 0; r < 4; r++) d[i][j][r] = 0.0f;

#define ISSUE_STAGE(st) do {                                                      \
    const int _s = (st) & (STAGES - 1);                                           \
    const char* _ab = Ag + (size_t)(st) * 128;                                    \
    const char* _bb = Bg + (size_t)(st) * 128;                                    \
    _Pragma("unroll")                                                             \
    for (int q = 0; q < 4; q++) {                                                 \
        int idx = tid + q * GTHREADS;                                             \
        uint32_t row = (uint32_t)(idx >> 3), u = (uint32_t)(idx & 7);             \
        cp16(sb + OFF_A + _s * 16384 + sw_off(row, u),                            \
             _ab + (size_t)row * rowBytes + u * 16);                              \
    }                                                                             \
    _Pragma("unroll")                                                             \
    for (int q = 0; q < 8; q++) {                                                 \
        int idx = tid + q * GTHREADS;                                             \
        uint32_t row = (uint32_t)(idx >> 3), u = (uint32_t)(idx & 7);             \
        cp16(sb + OFF_B + _s * 32768 + sw_off(row, u),                            \
             _bb + (size_t)row * rowBytes + u * 16);                              \
    }                                                                             \
} while (0)

    ISSUE_STAGE(0); CP_COMMIT();
    ISSUE_STAGE(1); CP_COMMIT();
    ISSUE_STAGE(2); CP_COMMIT();

    for (int kk = 0; kk < NITER; kk++) {
        CP_WAIT(2);
        __syncthreads();
        const int nx = kk + 3;
        if (nx < NITER) { ISSUE_STAGE(nx); CP_COMMIT(); }

        const uint32_t aB = sb + OFF_A + (kk & 3) * 16384;
        const uint32_t bB = sb + OFF_B + (kk & 3) * 32768;

#pragma unroll
        for (int hN = 0; hN < 2; hN++) {
            // fp16 accumulators for this K=64 stage, N-half (32 regs)
            unsigned dh[4][4][2];
#pragma unroll
            for (int i = 0; i < 4; i++)
#pragma unroll
                for (int jj = 0; jj < 4; jj++) { dh[i][jj][0] = 0u; dh[i][jj][1] = 0u; }

#pragma unroll
            for (int ks = 0; ks < 4; ks++) {
                const uint32_t ul = (uint32_t)(2 * ks);
                unsigned A4[4][4], B4[2][4];
#pragma unroll
                for (int i = 0; i < 4; i++) {
                    uint32_t row = aRowL + (uint32_t)(i * 16);
                    ldsm4(A4[i][0], A4[i][1], A4[i][2], A4[i][3],
                          aB + sw_off(row, ul + uA));
                }
#pragma unroll
                for (int j2 = 0; j2 < 2; j2++) {
                    uint32_t row = bRowL + (uint32_t)(hN * 32 + j2 * 16);
                    ldsm4(B4[j2][0], B4[j2][1], B4[j2][2], B4[j2][3],
                          bB + sw_off(row, ul + uB));
                }
#pragma unroll
                for (int i = 0; i < 4; i++)
#pragma unroll
                    for (int jj = 0; jj < 4; jj++)
                        mma_fp16h(dh[i][jj], A4[i], &B4[jj >> 1][2 * (jj & 1)]);
            }

            // promote this half into fp32
#pragma unroll
            for (int i = 0; i < 4; i++)
#pragma unroll
                for (int jj = 0; jj < 4; jj++) {
                    float2 f0 = __half22float2(*(const __half2*)&dh[i][jj][0]);
                    float2 f1 = __half22float2(*(const __half2*)&dh[i][jj][1]);
                    const int j = hN * 4 + jj;
                    d[i][j][0] += f0.x; d[i][j][1] += f0.y;
                    d[i][j][2] += f1.x; d[i][j][3] += f1.y;
                }
        }
    }

    // ---- epilogue: relu + contract with w2 slice ----
#pragma unroll
    for (int i = 0; i < 4; i++) {
#pragma unroll
        for (int h = 0; h < 2; h++) {
            const int row = mw * 64 + i * 16 + g4 + h * 8;
            float v0[8], v1[8];
#pragma unroll
            for (int j = 0; j < 8; j++) {
                v0[j] = fmaxf(d[i][j][2 * h + 0], 0.0f);
                v1[j] = fmaxf(d[i][j][2 * h + 1], 0.0f);
            }
#pragma unroll
            for (int c = 0; c < CDIM; c++) {
                float s = 0.0f;
#pragma unroll
                for (int j = 0; j < 8; j++) {
                    float2 w = *(const float2*)&W2s[c * BN + nw * 64 + j * 8 + 2 * t4];
                    s += v0[j] * w.x + v1[j] * w.y;
                }
                s += __shfl_xor_sync(0xFFFFFFFFu, s, 1);
                s += __shfl_xor_sync(0xFFFFFFFFu, s, 2);
                if (t4 == 0) atomicAdd(&Part[row * CDIM + c], s);
            }
        }
    }
    __syncthreads();

    float* outp = g_part + (size_t)nt * (MDIM * CDIM) + (size_t)(mt * BM) * CDIM;
    for (int p = tid; p < BM * CDIM; p += GTHREADS) outp[p] = Part[p];
#undef ISSUE_STAGE
}

// ---------------- reduce partials + log_softmax ----------------
__global__ void k_reduce(float* __restrict__ out) {   // <<<512, 320>>>
    const int tid = threadIdx.x;
    const int base = blockIdx.x * 32 * CDIM;
    float s = 0.0f;
#pragma unroll 8
    for (int nt = 0; nt < NT2; nt++)
        s += g_part[(size_t)nt * (MDIM * CDIM) + base + tid];
    __shared__ float L[32 * CDIM];
    L[tid] = s;
    __syncthreads();
    const int rl = tid / CDIM;
    float m = -INFINITY;
#pragma unroll
    for (int c = 0; c < CDIM; c++) m = fmaxf(m, L[rl * CDIM + c]);
    float se = 0.0f;
#pragma unroll
    for (int c = 0; c < CDIM; c++) se += expf(L[rl * CDIM + c] - m);
    out[base + tid] = s - m - logf(se);
}

// ---------------- launch ----------------
extern "C" void kernel_launch(void* const* d_in, const int* in_sizes, int n_in,
                              void* d_out, int out_size) {
    const float* x  = (const float*)d_in[0];
    const float* w1 = (const float*)d_in[1];
    const float* s1 = (const float*)d_in[2];
    const float* w2 = (const float*)d_in[3];
    const float* s2 = (const float*)d_in[4];
    float* out = (float*)d_out;

    cudaFuncSetAttribute(k_gemm1, cudaFuncAttributeMaxDynamicSharedMemorySize, SMEM_TOTAL);

    // launch order is load-bearing: ncu captures launch index 3 -> k_gemm1.
    k_select<<<SEL_NB, 256>>>(s1, NK1, J1, 0);                       // 0
    k_select2_w2m<<<1, 1024>>>(s2, w2, NK2, J2);                     // 1
    k_prep<<<W1_BLOCKS + XH_BLOCKS, 256>>>(w1, s1, x);               // 2
    dim3 grid(NT2, MDIM / BM);   // (32, 128)
    k_gemm1<<<grid, GTHREADS, SMEM_TOTAL>>>();                       // 3  <- ncu target
    k_reduce<<<MDIM / 32, 32 * CDIM>>>(out);                         // 4
}

// round 10
// speedup vs baseline: 1.5031x; 1.1021x over previous
#include <cuda_runtime.h>
#include <cuda_fp16.h>
#include <math.h>
#include <stdint.h>

// Problem dims
#define MDIM  16384
#define KDIM  784
#define KPAD  832                  // 13 chunks of 64 (zero padded)
#define NDIM  8192
#define CDIM  10
#define NK1   (NDIM * KDIM)        // 6,422,528
#define NK2   (CDIM * NDIM)        // 81,920
#define J1    3211264u             // int(0.5 * NK1)
#define J2    40960u               // int(0.5 * NK2)

// GEMM tiling: CTA 128x256, 256 threads, 8 warps as 2(M)x4(N), warp tile 64x64.
// Split-K fp16 accumulation: even stages -> dh_a, odd stages -> dh_b (no fp32 shadow).
#define BM 128
#define BN 256
#define KCH 64
#define NITER (KPAD / KCH)         // 13
#define STAGES 4
#define NT2 (NDIM / BN)            // 32 N-tiles
#define GTHREADS 256

// smem layout (dynamic) for GEMM
#define OFF_A 0                                   // STAGES x 16384
#define OFF_B (STAGES * 16384)                    // STAGES x 32768
#define OFF_W2 (OFF_B + STAGES * 32768)           // 196608
#define OFF_PART (OFF_W2 + CDIM * BN * 4)         // 206848
#define SMEM_TOTAL (OFF_PART + BM * CDIM * 4)     // 211968

#define SEL_NB 592                 // co-resident blocks for persistent select
#define W1_BLOCKS (NDIM * (KPAD / 4) / 256)       // 6656
#define XH_BLOCKS (MDIM * (KPAD / 8) / 256)       // 6656

// ---------------- scratch (device globals; no allocation allowed) ----------------
__device__ __half   g_xh[MDIM * KPAD];
__device__ __half   g_w1h[NDIM * KPAD];
__device__ float    g_w2m[CDIM * NDIM];
__device__ float    g_part[NT2 * MDIM * CDIM];
__device__ unsigned g_h1024[1024];
__device__ unsigned g_prefix;
__device__ unsigned g_rank;
__device__ unsigned g_nLess;
__device__ unsigned g_nTie;
__device__ unsigned g_T[2];
__device__ unsigned g_cutoff[2];
__device__ unsigned g_tieIdx[8192];
__device__ unsigned g_bar_cnt;
__device__ unsigned g_bar_gen;

__device__ __forceinline__ unsigned fbits_abs(float v) {
    return __float_as_uint(fabsf(v));
}
__device__ __forceinline__ uint32_t smem_u32(const void* p) {
    uint32_t a;
    asm("{ .reg .u64 t; cvta.to.shared.u64 t, %1; cvt.u32.u64 %0, t; }" : "=r"(a) : "l"(p));
    return a;
}

// ---------------- software grid barrier (all SEL_NB blocks co-resident) ----------------
__device__ __forceinline__ void grid_bar() {
    __syncthreads();
    if (threadIdx.x == 0) {
        unsigned gen = *((volatile unsigned*)&g_bar_gen);
        __threadfence();
        unsigned a = atomicAdd(&g_bar_cnt, 1u);
        if (a == SEL_NB - 1) {
            g_bar_cnt = 0;
            __threadfence();
            atomicAdd(&g_bar_gen, 1u);
        } else {
            while (*((volatile unsigned*)&g_bar_gen) == gen) { }
        }
        __threadfence();
    }
    __syncthreads();
}

// ---------------- persistent exact radix select for s1 (3 x 10-bit passes + ties) ----------------
__global__ void __launch_bounds__(256) k_select(const float* __restrict__ s, int n,
                                                unsigned j, int sel) {
    __shared__ unsigned h[1024];
    __shared__ unsigned sc[256];
    const int tid = threadIdx.x;
    const int gstride = SEL_NB * 256;
    const int gbase = blockIdx.x * 256 + tid;
    const float4* s4 = (const float4*)s;
    const int n4 = n >> 2;

    if (blockIdx.x == 0) {
        for (int b = tid; b < 1024; b += 256) g_h1024[b] = 0u;
        if (tid == 0) { g_prefix = 0u; g_rank = j; g_nLess = 0u; g_nTie = 0u; }
    }
    grid_bar();

#pragma unroll 1
    for (int pass = 0; pass < 3; pass++) {
        const int shift = 20 - 10 * pass;
        const unsigned prefix = g_prefix;
        for (int b = tid; b < 1024; b += 256) h[b] = 0u;
        __syncthreads();
        for (int i = gbase; i < n4; i += gstride) {
            float4 v = s4[i];
            unsigned b0 = fbits_abs(v.x), b1 = fbits_abs(v.y);
            unsigned b2 = fbits_abs(v.z), b3 = fbits_abs(v.w);
            if (pass == 0) {
                atomicAdd(&h[b0 >> 20], 1u); atomicAdd(&h[b1 >> 20], 1u);
                atomicAdd(&h[b2 >> 20], 1u); atomicAdd(&h[b3 >> 20], 1u);
            } else {
                if (((b0 ^ prefix) >> (shift + 10)) == 0u) atomicAdd(&h[(b0 >> shift) & 1023u], 1u);
                if (((b1 ^ prefix) >> (shift + 10)) == 0u) atomicAdd(&h[(b1 >> shift) & 1023u], 1u);
                if (((b2 ^ prefix) >> (shift + 10)) == 0u) atomicAdd(&h[(b2 >> shift) & 1023u], 1u);
                if (((b3 ^ prefix) >> (shift + 10)) == 0u) atomicAdd(&h[(b3 >> shift) & 1023u], 1u);
            }
        }
        __syncthreads();
        for (int b = tid; b < 1024; b += 256)
            if (h[b]) atomicAdd(&g_h1024[b], h[b]);
        grid_bar();

        if (blockIdx.x == 0) {
            unsigned c0 = g_h1024[4 * tid + 0], c1 = g_h1024[4 * tid + 1];
            unsigned c2 = g_h1024[4 * tid + 2], c3 = g_h1024[4 * tid + 3];
            unsigned mysum = c0 + c1 + c2 + c3;
            sc[tid] = mysum;
            __syncthreads();
#pragma unroll
            for (int off = 1; off < 256; off <<= 1) {
                unsigned v = (tid >= off) ? sc[tid - off] : 0u;
                __syncthreads();
                sc[tid] += v;
                __syncthreads();
            }
            unsigned incl = sc[tid], excl = incl - mysum;
            unsigned r = g_rank;
            if (excl <= r && r < incl) {
                unsigned d, cum = excl;
                if (r < cum + c0) { d = 4 * tid + 0; }
                else if (r < cum + c0 + c1) { d = 4 * tid + 1; cum += c0; }
                else if (r < cum + c0 + c1 + c2) { d = 4 * tid + 2; cum += c0 + c1; }
                else { d = 4 * tid + 3; cum += c0 + c1 + c2; }
                g_prefix = g_prefix | (d << shift);
                g_rank = r - cum;
            }
            __syncthreads();
            for (int b = tid; b < 1024; b += 256) g_h1024[b] = 0u;
            __threadfence();
        }
        grid_bar();
    }

    const unsigned T = g_prefix;
    unsigned nless = 0u;
    for (int i = gbase; i < n; i += gstride) {
        unsigned bits = fbits_abs(s[i]);
        if (bits < T) nless++;
        else if (bits == T) {
            unsigned p = atomicAdd(&g_nTie, 1u);
            if (p < 8192u) g_tieIdx[p] = (unsigned)i;
        }
    }
    sc[tid] = nless;
    __syncthreads();
#pragma unroll
    for (int off = 128; off > 0; off >>= 1) {
        if (tid < off) sc[tid] += sc[tid + off];
        __syncthreads();
    }
    if (tid == 0 && sc[0]) atomicAdd(&g_nLess, sc[0]);
    grid_bar();

    if (blockIdx.x == 0) {
        unsigned nLess = g_nLess;
        unsigned nTie = g_nTie; if (nTie > 8192u) nTie = 8192u;
        unsigned r2 = j - nLess;
        if (tid == 0) {
            g_T[sel] = T;
            if (r2 >= nTie) g_cutoff[sel] = 0xFFFFFFFFu;
        }
        __syncthreads();
        if (r2 < nTie) {
            for (unsigned t = tid; t < nTie; t += 256u) {
                unsigned mi = g_tieIdx[t];
                unsigned cnt = 0;
                for (unsigned u = 0; u < nTie; u++) cnt += (g_tieIdx[u] < mi) ? 1u : 0u;
                if (cnt == r2) g_cutoff[sel] = mi;
            }
        }
    }
}

// ---------------- single-block select for s2 + fused w2 mask build ----------------
__global__ void __launch_bounds__(1024) k_select2_w2m(const float* __restrict__ s,
                                                      const float* __restrict__ w2,
                                                      int n, unsigned j) {
    __shared__ unsigned h[1024];
    __shared__ unsigned sc[1024];
    __shared__ unsigned tie[4096];
    __shared__ unsigned sPrefix, sRank, sNTie, sNLess, sCut;
    const int tid = threadIdx.x;
    const float4* s4 = (const float4*)s;
    const int n4 = n >> 2;

    if (tid == 0) { sPrefix = 0u; sRank = j; sNTie = 0u; sNLess = 0u; sCut = 0xFFFFFFFFu; }
    __syncthreads();

#pragma unroll 1
    for (int pass = 0; pass < 3; pass++) {
        const int shift = 20 - 10 * pass;
        const unsigned prefix = sPrefix;
        h[tid] = 0u;
        __syncthreads();
        for (int i = tid; i < n4; i += 1024) {
            float4 v = s4[i];
            unsigned b0 = fbits_abs(v.x), b1 = fbits_abs(v.y);
            unsigned b2 = fbits_abs(v.z), b3 = fbits_abs(v.w);
            if (pass == 0) {
                atomicAdd(&h[b0 >> 20], 1u); atomicAdd(&h[b1 >> 20], 1u);
                atomicAdd(&h[b2 >> 20], 1u); atomicAdd(&h[b3 >> 20], 1u);
            } else {
                if (((b0 ^ prefix) >> (shift + 10)) == 0u) atomicAdd(&h[(b0 >> shift) & 1023u], 1u);
                if (((b1 ^ prefix) >> (shift + 10)) == 0u) atomicAdd(&h[(b1 >> shift) & 1023u], 1u);
                if (((b2 ^ prefix) >> (shift + 10)) == 0u) atomicAdd(&h[(b2 >> shift) & 1023u], 1u);
                if (((b3 ^ prefix) >> (shift + 10)) == 0u) atomicAdd(&h[(b3 >> shift) & 1023u], 1u);
            }
        }
        __syncthreads();
        unsigned mine = h[tid];
        sc[tid] = mine;
        __syncthreads();
#pragma unroll
        for (int off = 1; off < 1024; off <<= 1) {
            unsigned v = (tid >= off) ? sc[tid - off] : 0u;
            __syncthreads();
            sc[tid] += v;
            __syncthreads();
        }
        unsigned incl = sc[tid], excl = incl - mine;
        unsigned r = sRank;
        __syncthreads();
        if (excl <= r && r < incl) {
            sPrefix = prefix | ((unsigned)tid << shift);
            sRank = r - excl;
        }
        __syncthreads();
    }

    const unsigned T = sPrefix;
    unsigned nless = 0u;
    for (int i = tid; i < n; i += 1024) {
        unsigned bits = fbits_abs(s[i]);
        if (bits < T) nless++;
        else if (bits == T) {
            unsigned p = atomicAdd(&sNTie, 1u);
            if (p < 4096u) tie[p] = (unsigned)i;
        }
    }
    sc[tid] = nless;
    __syncthreads();
#pragma unroll
    for (int off = 512; off > 0; off >>= 1) {
        if (tid < off) sc[tid] += sc[tid + off];
        __syncthreads();
    }
    if (tid == 0) sNLess = sc[0];
    __syncthreads();

    {
        unsigned nTie = sNTie; if (nTie > 4096u) nTie = 4096u;
        unsigned r2 = j - sNLess;
        if (r2 < nTie) {
            for (unsigned t = tid; t < nTie; t += 1024u) {
                unsigned mi = tie[t];
                unsigned cnt = 0;
                for (unsigned u = 0; u < nTie; u++) cnt += (tie[u] < mi) ? 1u : 0u;
                if (cnt == r2) sCut = mi;
            }
        }
    }
    __syncthreads();
    const unsigned cut = sCut;
    if (tid == 0) { g_T[1] = T; g_cutoff[1] = cut; }

    for (int i = tid; i < n; i += 1024) {
        unsigned bits = fbits_abs(s[i]);
        bool keep = (bits > T) || (bits == T && (unsigned)i >= cut);
        g_w2m[i] = keep ? w2[i] : 0.0f;
    }
}

// ---------------- fused prep: masked fp16 w1 + fp16 x (both KPAD layout) ----------------
__global__ void __launch_bounds__(256) k_prep(const float* __restrict__ w1,
                                              const float* __restrict__ s1,
                                              const float* __restrict__ x) {
    const int b = blockIdx.x;
    const int tid = threadIdx.x;
    if (b < W1_BLOCKS) {
        int i = b * 256 + tid;
        int row = i / (KPAD / 4), k4 = (i % (KPAD / 4)) * 4;
        __half2 o[2];
        if (k4 < KDIM) {
            int src = row * KDIM + k4;
            float4 w = *(const float4*)(w1 + src);
            float4 sv = *(const float4*)(s1 + src);
            unsigned T = g_T[0], cut = g_cutoff[0];
            unsigned b0 = fbits_abs(sv.x), b1 = fbits_abs(sv.y);
            unsigned b2 = fbits_abs(sv.z), b3 = fbits_abs(sv.w);
            float f0 = ((b0 > T) || (b0 == T && (unsigned)(src + 0) >= cut)) ? w.x : 0.0f;
            float f1 = ((b1 > T) || (b1 == T && (unsigned)(src + 1) >= cut)) ? w.y : 0.0f;
            float f2 = ((b2 > T) || (b2 == T && (unsigned)(src + 2) >= cut)) ? w.z : 0.0f;
            float f3 = ((b3 > T) || (b3 == T && (unsigned)(src + 3) >= cut)) ? w.w : 0.0f;
            o[0] = __floats2half2_rn(f0, f1);
            o[1] = __floats2half2_rn(f2, f3);
        } else {
            o[0] = o[1] = __floats2half2_rn(0.0f, 0.0f);
        }
        *(uint2*)(g_w1h + (size_t)row * KPAD + k4) = *(const uint2*)o;
    } else {
        int i = (b - W1_BLOCKS) * 256 + tid;
        int row = i / (KPAD / 8), u = i % (KPAD / 8);
        int c8 = u * 8;
        __half2 h[4];
        if (c8 < KDIM) {
            const float4* p = (const float4*)(x + (size_t)row * KDIM + c8);
            float4 v0 = p[0], v1 = p[1];
            h[0] = __floats2half2_rn(v0.x, v0.y);
            h[1] = __floats2half2_rn(v0.z, v0.w);
            h[2] = __floats2half2_rn(v1.x, v1.y);
            h[3] = __floats2half2_rn(v1.z, v1.w);
        } else {
            h[0] = h[1] = h[2] = h[3] = __floats2half2_rn(0.0f, 0.0f);
        }
        *(uint4*)(g_xh + (size_t)row * KPAD + c8) = *(const uint4*)h;
    }
}

// ---------------- GEMM helpers ----------------
__device__ __forceinline__ void cp16(uint32_t dst, const void* src) {
    asm volatile("cp.async.cg.shared.global [%0], [%1], 16;" :: "r"(dst), "l"(src));
}
#define CP_COMMIT() asm volatile("cp.async.commit_group;" ::: "memory")
#define CP_WAIT(n)  asm volatile("cp.async.wait_group %0;" :: "n"(n) : "memory")

__device__ __forceinline__ void ldsm4(unsigned& r0, unsigned& r1, unsigned& r2, unsigned& r3,
                                      uint32_t addr) {
    asm volatile("ldmatrix.sync.aligned.m8n8.x4.shared.b16 {%0,%1,%2,%3}, [%4];"
                 : "=r"(r0), "=r"(r1), "=r"(r2), "=r"(r3) : "r"(addr));
}

// fp16-accumulating MMA: D,C are 2 regs (4 halves)
__device__ __forceinline__ void mma_fp16h(unsigned* d, const unsigned* a, const unsigned* b) {
    asm volatile(
        "mma.sync.aligned.m16n8k16.row.col.f16.f16.f16.f16 "
        "{%0,%1}, {%2,%3,%4,%5}, {%6,%7}, {%0,%1};\n"
        : "+r"(d[0]), "+r"(d[1])
        : "r"(a[0]), "r"(a[1]), "r"(a[2]), "r"(a[3]), "r"(b[0]), "r"(b[1]));
}

__device__ __forceinline__ uint32_t sw_off(uint32_t row, uint32_t u) {
    return row * 128u + ((u ^ (row & 7u)) << 4);
}

// ---------------- GEMM1: 256 threads, 8 warps of 64x64, split-K fp16 accumulation.
//  Even K=64 stages accumulate into dh_a, odd into dh_b (both fp16, 64 regs each).
//  No fp32 shadow accumulator -> no register spill. Final add in fp32 at epilogue.
__global__ void __launch_bounds__(GTHREADS, 1) k_gemm1() {
    extern __shared__ __align__(1024) char smem[];
    const uint32_t sb = smem_u32(smem);
    const int tid = threadIdx.x;
    const int nt = blockIdx.x;   // 0..31 (N tiles of 256)
    const int mt = blockIdx.y;   // 0..127 (M tiles of 128)

    const int wid = tid >> 5, lane = tid & 31;
    const int mw = wid & 1;      // 2 M warp-blocks of 64
    const int nw = wid >> 1;     // 4 N warp-blocks of 64
    const int g4 = lane >> 2, t4 = lane & 3;
    const int r8 = lane & 7;

    float* W2s  = (float*)(smem + OFF_W2);
    float* Part = (float*)(smem + OFF_PART);
    for (int p = tid; p < CDIM * BN; p += GTHREADS)
        W2s[p] = g_w2m[(p >> 8) * NDIM + nt * BN + (p & 255)];
    for (int p = tid; p < BM * CDIM; p += GTHREADS)
        Part[p] = 0.0f;

    const char* Ag = (const char*)(g_xh  + (size_t)(mt * BM) * KPAD);
    const char* Bg = (const char*)(g_w1h + (size_t)(nt * BN) * KPAD);
    const size_t rowBytes = KPAD * 2;

    const uint32_t aRowL = (uint32_t)(mw * 64 + ((lane >> 3) & 1) * 8 + r8);
    const uint32_t uA    = (uint32_t)(lane >> 4);
    const uint32_t bRowL = (uint32_t)(nw * 64 + (lane >> 4) * 8 + r8);
    const uint32_t uB    = (uint32_t)((lane >> 3) & 1);

    // two fp16 accumulator sets (64 regs each), no fp32 shadow
    unsigned dh_a[4][8][2], dh_b[4][8][2];
#pragma unroll
    for (int i = 0; i < 4; i++)
#pragma unroll
        for (int j = 0; j < 8; j++) {
            dh_a[i][j][0] = 0u; dh_a[i][j][1] = 0u;
            dh_b[i][j][0] = 0u; dh_b[i][j][1] = 0u;
        }

#define ISSUE_STAGE(st) do {                                                      \
    const int _s = (st) & (STAGES - 1);                                           \
    const char* _ab = Ag + (size_t)(st) * 128;                                    \
    const char* _bb = Bg + (size_t)(st) * 128;                                    \
    _Pragma("unroll")                                                             \
    for (int q = 0; q < 4; q++) {                                                 \
        int idx = tid + q * GTHREADS;                                             \
        uint32_t row = (uint32_t)(idx >> 3), u = (uint32_t)(idx & 7);             \
        cp16(sb + OFF_A + _s * 16384 + sw_off(row, u),                            \
             _ab + (size_t)row * rowBytes + u * 16);                              \
    }                                                                             \
    _Pragma("unroll")                                                             \
    for (int q = 0; q < 8; q++) {                                                 \
        int idx = tid + q * GTHREADS;                                             \
        uint32_t row = (uint32_t)(idx >> 3), u = (uint32_t)(idx & 7);             \
        cp16(sb + OFF_B + _s * 32768 + sw_off(row, u),                            \
             _bb + (size_t)row * rowBytes + u * 16);                              \
    }                                                                             \
} while (0)

// One pipeline stage: wait for stage kk's data, prefetch stage kk+3, compute
// 4 K=16 slices into the named fp16 accumulator set DH. CP_COMMIT is
// unconditional so wait_group(2) always guards exactly stage kk's group.
#define STAGE(kk, DH) do {                                                        \
    CP_WAIT(2);                                                                   \
    __syncthreads();                                                              \
    const int _nx = (kk) + 3;                                                     \
    if (_nx < NITER) ISSUE_STAGE(_nx);                                            \
    CP_COMMIT();                                                                  \
    const uint32_t aB = sb + OFF_A + ((kk) & 3) * 16384;                          \
    const uint32_t bB = sb + OFF_B + ((kk) & 3) * 32768;                          \
    _Pragma("unroll")                                                             \
    for (int ks = 0; ks < 4; ks++) {                                              \
        const uint32_t ul = (uint32_t)(2 * ks);                                   \
        unsigned A4[4][4], B4[4][4];                                              \
        _Pragma("unroll")                                                         \
        for (int i = 0; i < 4; i++) {                                             \
            uint32_t row = aRowL + (uint32_t)(i * 16);                            \
            ldsm4(A4[i][0], A4[i][1], A4[i][2], A4[i][3],                         \
                  aB + sw_off(row, ul + uA));                                     \
        }                                                                         \
        _Pragma("unroll")                                                         \
        for (int j2 = 0; j2 < 4; j2++) {                                          \
            uint32_t row = bRowL + (uint32_t)(j2 * 16);                           \
            ldsm4(B4[j2][0], B4[j2][1], B4[j2][2], B4[j2][3],                     \
                  bB + sw_off(row, ul + uB));                                     \
        }                                                                         \
        _Pragma("unroll")                                                         \
        for (int i = 0; i < 4; i++)                                               \
            _Pragma("unroll")                                                     \
            for (int j = 0; j < 8; j++)                                           \
                mma_fp16h(DH[i][j], A4[i], &B4[j >> 1][2 * (j & 1)]);             \
    }                                                                             \
} while (0)

    ISSUE_STAGE(0); CP_COMMIT();
    ISSUE_STAGE(1); CP_COMMIT();
    ISSUE_STAGE(2); CP_COMMIT();

    // 13 stages: even -> dh_a, odd -> dh_b (static selection; no dynamic indexing)
#pragma unroll 1
    for (int kb = 0; kb < 6; kb++) {
        STAGE(2 * kb + 0, dh_a);
        STAGE(2 * kb + 1, dh_b);
    }
    STAGE(12, dh_a);

    // ---- epilogue: combine split-K halves in fp32, relu, contract with w2 slice ----
#pragma unroll
    for (int i = 0; i < 4; i++) {
#pragma unroll
        for (int h = 0; h < 2; h++) {
            const int row = mw * 64 + i * 16 + g4 + h * 8;
            float v0[8], v1[8];
#pragma unroll
            for (int j = 0; j < 8; j++) {
                float2 fa = __half22float2(*(const __half2*)&dh_a[i][j][h]);
                float2 fb = __half22float2(*(const __half2*)&dh_b[i][j][h]);
                v0[j] = fmaxf(fa.x + fb.x, 0.0f);
                v1[j] = fmaxf(fa.y + fb.y, 0.0f);
            }
#pragma unroll
            for (int c = 0; c < CDIM; c++) {
                float s = 0.0f;
#pragma unroll
                for (int j = 0; j < 8; j++) {
                    float2 w = *(const float2*)&W2s[c * BN + nw * 64 + j * 8 + 2 * t4];
                    s += v0[j] * w.x + v1[j] * w.y;
                }
                s += __shfl_xor_sync(0xFFFFFFFFu, s, 1);
                s += __shfl_xor_sync(0xFFFFFFFFu, s, 2);
                if (t4 == 0) atomicAdd(&Part[row * CDIM + c], s);
            }
        }
    }
    __syncthreads();

    float* outp = g_part + (size_t)nt * (MDIM * CDIM) + (size_t)(mt * BM) * CDIM;
    for (int p = tid; p < BM * CDIM; p += GTHREADS) outp[p] = Part[p];
#undef STAGE
#undef ISSUE_STAGE
}

// ---------------- reduce partials + log_softmax ----------------
__global__ void k_reduce(float* __restrict__ out) {   // <<<512, 320>>>
    const int tid = threadIdx.x;
    const int base = blockIdx.x * 32 * CDIM;
    float s = 0.0f;
#pragma unroll 8
    for (int nt = 0; nt < NT2; nt++)
        s += g_part[(size_t)nt * (MDIM * CDIM) + base + tid];
    __shared__ float L[32 * CDIM];
    L[tid] = s;
    __syncthreads();
    const int rl = tid / CDIM;
    float m = -INFINITY;
#pragma unroll
    for (int c = 0; c < CDIM; c++) m = fmaxf(m, L[rl * CDIM + c]);
    float se = 0.0f;
#pragma unroll
    for (int c = 0; c < CDIM; c++) se += expf(L[rl * CDIM + c] - m);
    out[base + tid] = s - m - logf(se);
}

// ---------------- launch ----------------
extern "C" void kernel_launch(void* const* d_in, const int* in_sizes, int n_in,
                              void* d_out, int out_size) {
    const float* x  = (const float*)d_in[0];
    const float* w1 = (const float*)d_in[1];
    const float* s1 = (const float*)d_in[2];
    const float* w2 = (const float*)d_in[3];
    const float* s2 = (const float*)d_in[4];
    float* out = (float*)d_out;

    cudaFuncSetAttribute(k_gemm1, cudaFuncAttributeMaxDynamicSharedMemorySize, SMEM_TOTAL);

    // launch order is load-bearing: ncu captures launch index 3 -> k_gemm1.
    k_select<<<SEL_NB, 256>>>(s1, NK1, J1, 0);                       // 0
    k_select2_w2m<<<1, 1024>>>(s2, w2, NK2, J2);                     // 1
    k_prep<<<W1_BLOCKS + XH_BLOCKS, 256>>>(w1, s1, x);               // 2
    dim3 grid(NT2, MDIM / BM);   // (32, 128)
    k_gemm1<<<grid, GTHREADS, SMEM_TOTAL>>>();                       // 3  <- ncu target
    k_reduce<<<MDIM / 32, 32 * CDIM>>>(out);                         // 4
}